// round 11
// baseline (speedup 1.0000x reference)
#include <cuda_runtime.h>
#include <cstdint>

#define BATCH_ 16
#define SEQ_   2048
#define LIN_   256
#define MENC_  512
#define HD_    1024
#define FMLP_  4096
#define CH_    16
#define NCH_   128
#define ROWS_  (NCH_*BATCH_)        // 2048
#define APRON_ 1024
#define FROWS_ (APRON_ + ROWS_)     // 3072

// ---------- scratch (device globals; allocation is forbidden) ----------
__device__ float g_Wx[LIN_*HD_];
__device__ float g_bvec[HD_];
__device__ float g_Bu[(size_t)BATCH_*SEQ_*HD_];
__device__ float g_P0[HD_*HD_];
__device__ float g_P1[HD_*HD_];
__device__ float g_FA[(size_t)FROWS_*HD_];
__device__ float g_FB[(size_t)FROWS_*HD_];
__device__ float g_Z [BATCH_*HD_];
__device__ float g_HL[BATCH_*HD_];
__device__ float g_T [BATCH_*FMLP_];

#define GF_BIAS   1
#define GF_SADD   2
#define GF_SSTORE 4
#define GF_ADDM   8

struct GA {
    const float* A; const float* B; float* C;
    const float* bias; const float* scanB; float* scanO; const float* addM;
    int lda, N, K, jstep, flags;
};

static inline GA mkGA(const float* A, int lda, const float* B, float* C,
                      int N, int K, int flags,
                      const float* bias = nullptr,
                      const float* scanB = nullptr, float* scanO = nullptr,
                      const float* addM = nullptr, int jstep = 0)
{
    GA g; g.A = A; g.B = B; g.C = C; g.bias = bias; g.scanB = scanB;
    g.scanO = scanO; g.addM = addM; g.lda = lda; g.N = N; g.K = K;
    g.jstep = jstep; g.flags = flags; return g;
}

// 64(m) x 128(n) tile, 128 threads, 8x8 micro-tile, packed f32x2 FMA.
// A-pairs along m come straight from LDS.128 of the k-major transposed
// A tile; 2 B/FFMA2 smem economy (crossbar and fma pipe balanced).
__device__ __forceinline__ void gemm_core(const GA& g,
                                          float (&As)[2][16][68],
                                          float (&Bs)[2][16][132],
                                          int bxi, int byi)
{
    const int tid = threadIdx.x;
    const int tm = tid >> 4, tn = tid & 15;
    const int m0 = byi * 64, n0 = bxi * 128;
    const int lar = tid >> 1, lac = (tid & 1) * 8;
    const int lbr = tid >> 3, lbc = (tid & 7) * 16;
    const int N = g.N, K = g.K;

    const float* Aload = g.A + (size_t)(m0 + lar) * g.lda + lac;
    const float* Bload = g.B + (size_t)lbr * N + n0 + lbc;

    unsigned long long acc[4][8];
#pragma unroll
    for (int p = 0; p < 4; p++)
#pragma unroll
        for (int q = 0; q < 8; q++) acc[p][q] = 0ull;

    float4 a0 = *(const float4*)(Aload);
    float4 a1 = *(const float4*)(Aload + 4);
    float4 b0 = *(const float4*)(Bload);
    float4 b1 = *(const float4*)(Bload + 4);
    float4 b2 = *(const float4*)(Bload + 8);
    float4 b3 = *(const float4*)(Bload + 12);
    As[0][lac+0][lar]=a0.x; As[0][lac+1][lar]=a0.y; As[0][lac+2][lar]=a0.z; As[0][lac+3][lar]=a0.w;
    As[0][lac+4][lar]=a1.x; As[0][lac+5][lar]=a1.y; As[0][lac+6][lar]=a1.z; As[0][lac+7][lar]=a1.w;
    *(float4*)&Bs[0][lbr][lbc]      = b0;
    *(float4*)&Bs[0][lbr][lbc + 4]  = b1;
    *(float4*)&Bs[0][lbr][lbc + 8]  = b2;
    *(float4*)&Bs[0][lbr][lbc + 12] = b3;
    __syncthreads();

    int buf = 0;
    for (int kt = 0; kt < K; kt += 16) {
        const bool more = (kt + 16) < K;
        if (more) {
            a0 = *(const float4*)(Aload + kt + 16);
            a1 = *(const float4*)(Aload + kt + 20);
            const float* Bk = Bload + (size_t)(kt + 16) * N;
            b0 = *(const float4*)(Bk);
            b1 = *(const float4*)(Bk + 4);
            b2 = *(const float4*)(Bk + 8);
            b3 = *(const float4*)(Bk + 12);
        }
#pragma unroll
        for (int k = 0; k < 16; k++) {
            const ulonglong2 pa0 = *(const ulonglong2*)&As[buf][k][tm * 8];
            const ulonglong2 pa1 = *(const ulonglong2*)&As[buf][k][tm * 8 + 4];
            const float4 x = *(const float4*)&Bs[buf][k][tn * 8];
            const float4 y = *(const float4*)&Bs[buf][k][tn * 8 + 4];
            unsigned long long pb[8];
            asm("mov.b64 %0,{%1,%1};" : "=l"(pb[0]) : "f"(x.x));
            asm("mov.b64 %0,{%1,%1};" : "=l"(pb[1]) : "f"(x.y));
            asm("mov.b64 %0,{%1,%1};" : "=l"(pb[2]) : "f"(x.z));
            asm("mov.b64 %0,{%1,%1};" : "=l"(pb[3]) : "f"(x.w));
            asm("mov.b64 %0,{%1,%1};" : "=l"(pb[4]) : "f"(y.x));
            asm("mov.b64 %0,{%1,%1};" : "=l"(pb[5]) : "f"(y.y));
            asm("mov.b64 %0,{%1,%1};" : "=l"(pb[6]) : "f"(y.z));
            asm("mov.b64 %0,{%1,%1};" : "=l"(pb[7]) : "f"(y.w));
#pragma unroll
            for (int q = 0; q < 8; q++) {
                asm("fma.rn.f32x2 %0,%1,%2,%0;" : "+l"(acc[0][q]) : "l"(pa0.x), "l"(pb[q]));
                asm("fma.rn.f32x2 %0,%1,%2,%0;" : "+l"(acc[1][q]) : "l"(pa0.y), "l"(pb[q]));
                asm("fma.rn.f32x2 %0,%1,%2,%0;" : "+l"(acc[2][q]) : "l"(pa1.x), "l"(pb[q]));
                asm("fma.rn.f32x2 %0,%1,%2,%0;" : "+l"(acc[3][q]) : "l"(pa1.y), "l"(pb[q]));
            }
        }
        if (more) {
            const int nb = buf ^ 1;
            As[nb][lac+0][lar]=a0.x; As[nb][lac+1][lar]=a0.y; As[nb][lac+2][lar]=a0.z; As[nb][lac+3][lar]=a0.w;
            As[nb][lac+4][lar]=a1.x; As[nb][lac+5][lar]=a1.y; As[nb][lac+6][lar]=a1.z; As[nb][lac+7][lar]=a1.w;
            *(float4*)&Bs[nb][lbr][lbc]      = b0;
            *(float4*)&Bs[nb][lbr][lbc + 4]  = b1;
            *(float4*)&Bs[nb][lbr][lbc + 8]  = b2;
            *(float4*)&Bs[nb][lbr][lbc + 12] = b3;
            __syncthreads();
        }
        buf ^= 1;
    }

    float cv[8][8];
#pragma unroll
    for (int p = 0; p < 4; p++)
#pragma unroll
        for (int q = 0; q < 8; q++)
            asm("mov.b64 {%0,%1},%2;"
                : "=f"(cv[2*p][q]), "=f"(cv[2*p+1][q]) : "l"(acc[p][q]));

    const int F = g.flags;
    const int gc = n0 + tn * 8;
    float4 bv0 = make_float4(0.f,0.f,0.f,0.f), bv1 = bv0;
    if (F & GF_BIAS) {
        bv0 = *(const float4*)(g.bias + gc);
        bv1 = *(const float4*)(g.bias + gc + 4);
    }
#pragma unroll
    for (int mr = 0; mr < 8; mr++) {
        const int gm = m0 + tm * 8 + mr;
        float4 v0 = make_float4(cv[mr][0], cv[mr][1], cv[mr][2], cv[mr][3]);
        float4 v1 = make_float4(cv[mr][4], cv[mr][5], cv[mr][6], cv[mr][7]);
        if (F & GF_BIAS) {
            v0.x += bv0.x; v0.y += bv0.y; v0.z += bv0.z; v0.w += bv0.w;
            v1.x += bv1.x; v1.y += bv1.y; v1.z += bv1.z; v1.w += bv1.w;
        }
        if (F & GF_ADDM) {
            float4 u0 = *(const float4*)(g.addM + (size_t)gm * N + gc);
            float4 u1 = *(const float4*)(g.addM + (size_t)gm * N + gc + 4);
            v0.x += u0.x; v0.y += u0.y; v0.z += u0.z; v0.w += u0.w;
            v1.x += u1.x; v1.y += u1.y; v1.z += u1.z; v1.w += u1.w;
        }
        size_t soff = 0;
        if (F & (GF_SADD | GF_SSTORE))
            soff = ((size_t)(gm & 15) * SEQ_ + (size_t)(gm >> 4) * CH_ + g.jstep) * HD_ + gc;
        if (F & GF_SADD) {
            float4 s0 = *(const float4*)(g.scanB + soff);
            float4 s1 = *(const float4*)(g.scanB + soff + 4);
            v0.x += s0.x; v0.y += s0.y; v0.z += s0.z; v0.w += s0.w;
            v1.x += s1.x; v1.y += s1.y; v1.z += s1.z; v1.w += s1.w;
        }
        *(float4*)(g.C + (size_t)gm * N + gc)     = v0;
        *(float4*)(g.C + (size_t)gm * N + gc + 4) = v1;
        if (F & GF_SSTORE) {
            *(float4*)(g.scanO + soff)     = v0;
            *(float4*)(g.scanO + soff + 4) = v1;
        }
    }
}

__global__ void __launch_bounds__(128) gemm_one(GA g)
{
    __shared__ float As[2][16][68];
    __shared__ float Bs[2][16][132];
    gemm_core(g, As, Bs, blockIdx.x, blockIdx.y);
}

// Two independent GEMM segments in one launch (split on blockIdx.y):
// hides the serial P-squaring chain behind the scan/prefix steps.
__global__ void __launch_bounds__(128) gemm_two(GA g1, GA g2, int bySplit)
{
    __shared__ float As[2][16][68];
    __shared__ float Bs[2][16][132];
    if ((int)blockIdx.y < bySplit)
        gemm_core(g1, As, Bs, blockIdx.x, blockIdx.y);
    else
        gemm_core(g2, As, Bs, blockIdx.x, blockIdx.y - bySplit);
}

#define SF_BIAS 1
#define SF_RELU 2
#define SF_ADD  4

// Small-M (<=16) GEMM: per block 16 rows x 64 cols, 256 threads.
template<int F>
__global__ void __launch_bounds__(256)
sgemm16(const float* __restrict__ Ap, long lda,
        const float* __restrict__ Bp, int ldb,
        float* __restrict__ Cp, int ldc,
        const float* __restrict__ bias,
        const float* __restrict__ addend, long ldadd,
        int M, int K)
{
    __shared__ float As[16][33];
    const int tid = threadIdx.x;
    const int c = tid & 63, g = tid >> 6;
    const int col = blockIdx.x * 64 + c;
    float acc[4] = {0.f, 0.f, 0.f, 0.f};
    for (int k0 = 0; k0 < K; k0 += 32) {
        __syncthreads();
        for (int e = tid; e < 512; e += 256) {
            const int r = e >> 5, kk = e & 31;
            As[r][kk] = (r < M) ? Ap[(size_t)r * lda + k0 + kk] : 0.f;
        }
        __syncthreads();
#pragma unroll 8
        for (int kk = 0; kk < 32; kk++) {
            const float bv = Bp[(size_t)(k0 + kk) * ldb + col];
#pragma unroll
            for (int i = 0; i < 4; i++) acc[i] += As[g * 4 + i][kk] * bv;
        }
    }
#pragma unroll
    for (int i = 0; i < 4; i++) {
        const int r = g * 4 + i;
        if (r < M) {
            float v = acc[i];
            if (F & SF_BIAS) v += bias[col];
            if (F & SF_ADD)  v += addend[(size_t)r * ldadd + col];
            if (F & SF_RELU) v = fmaxf(v, 0.f);
            Cp[(size_t)r * ldc + col] = v;
        }
    }
}

__global__ void __launch_bounds__(256)
ln16(const float* __restrict__ z, const float* __restrict__ gam,
     const float* __restrict__ bet, float* __restrict__ o)
{
    __shared__ float s1[8], s2[8];
    const int b = blockIdx.x, tid = threadIdx.x;
    float4 v = ((const float4*)(z + (size_t)b * HD_))[tid];
    float s = v.x + v.y + v.z + v.w;
    float q = v.x*v.x + v.y*v.y + v.z*v.z + v.w*v.w;
    for (int d = 16; d > 0; d >>= 1) {
        s += __shfl_xor_sync(0xffffffffu, s, d);
        q += __shfl_xor_sync(0xffffffffu, q, d);
    }
    if ((tid & 31) == 0) { s1[tid >> 5] = s; s2[tid >> 5] = q; }
    __syncthreads();
    if (tid < 8) {
        s = s1[tid]; q = s2[tid];
        for (int d = 4; d > 0; d >>= 1) {
            s += __shfl_xor_sync(0xffu, s, d);
            q += __shfl_xor_sync(0xffu, q, d);
        }
        if (tid == 0) { s1[0] = s; s2[0] = q; }
    }
    __syncthreads();
    const float mu = s1[0] * (1.f / HD_);
    const float var = s2[0] * (1.f / HD_) - mu * mu;
    const float rs = rsqrtf(var + 1e-5f);
    float4 gg = ((const float4*)gam)[tid];
    float4 bb = ((const float4*)bet)[tid];
    float4 r;
    r.x = (v.x - mu) * rs * gg.x + bb.x;
    r.y = (v.y - mu) * rs * gg.y + bb.y;
    r.z = (v.z - mu) * rs * gg.z + bb.z;
    r.w = (v.w - mu) * rs * gg.w + bb.w;
    ((float4*)(o + (size_t)b * HD_))[tid] = r;
}

// phase-1 init: local state at j=0 is Bu[b, c*CH, :]
__global__ void gatherBu(const float* __restrict__ Bu, float* __restrict__ H)
{
    const int r = blockIdx.x;
    const size_t src = ((size_t)(r & 15) * SEQ_ + (size_t)(r >> 4) * CH_) * HD_;
    ((float4*)(H + (size_t)r * HD_))[threadIdx.x] =
        ((const float4*)(Bu + src))[threadIdx.x];
}

__global__ void zero4(float* p)
{
    ((float4*)p)[(size_t)blockIdx.x * 256 + threadIdx.x] = make_float4(0.f, 0.f, 0.f, 0.f);
}

extern "C" void kernel_launch(void* const* d_in, const int* in_sizes, int n_in,
                              void* d_out, int out_size)
{
    (void)in_sizes; (void)n_in; (void)out_size;
    const float* x    = (const float*)d_in[0];
    const float* Wenc = (const float*)d_in[1];
    const float* benc = (const float*)d_in[2];
    const float* WB   = (const float*)d_in[3];
    const float* Amat = (const float*)d_in[4];
    const float* Wres = (const float*)d_in[5];
    const float* bres = (const float*)d_in[6];
    const float* lng  = (const float*)d_in[7];
    const float* lnb  = (const float*)d_in[8];
    const float* W1   = (const float*)d_in[9];
    const float* b1   = (const float*)d_in[10];
    const float* W2   = (const float*)d_in[11];
    const float* b2   = (const float*)d_in[12];
    float* out0 = (float*)d_out;                 // (16,1024) MLP head
    float* outH = out0 + BATCH_ * HD_;           // (16,2048,1024) H_seq_pre

    float *Wx, *bvec, *Bu, *P0, *P1, *FA, *FB, *Z, *HL, *T;
    cudaGetSymbolAddress((void**)&Wx,   g_Wx);
    cudaGetSymbolAddress((void**)&bvec, g_bvec);
    cudaGetSymbolAddress((void**)&Bu,   g_Bu);
    cudaGetSymbolAddress((void**)&P0,   g_P0);
    cudaGetSymbolAddress((void**)&P1,   g_P1);
    cudaGetSymbolAddress((void**)&FA,   g_FA);
    cudaGetSymbolAddress((void**)&FB,   g_FB);
    cudaGetSymbolAddress((void**)&Z,    g_Z);
    cudaGetSymbolAddress((void**)&HL,   g_HL);
    cudaGetSymbolAddress((void**)&T,    g_T);

    const size_t AP = (size_t)APRON_ * HD_;

    // 1) Wx = W_enc @ W_B ; bvec = b_enc @ W_B
    gemm_one<<<dim3(8, 4), 128>>>(mkGA(Wenc, MENC_, WB, Wx, HD_, MENC_, 0));
    sgemm16<0><<<16, 256>>>(benc, MENC_, WB, HD_, bvec, HD_,
                            nullptr, nullptr, 0, 1, MENC_);

    // 2) Bu = x2d @ Wx + bvec   (32768 x 1024, K=256)
    gemm_one<<<dim3(8, 512), 128>>>(mkGA(x, LIN_, Wx, Bu, HD_, LIN_, GF_BIAS, bvec));

    // 3) zero aprons (1024 rows each buffer)
    zero4<<<1024, 256>>>(FA);
    zero4<<<1024, 256>>>(FB);

    // 4) Phase 1: local scans from zero (15 serial steps, M=2048).
    //    First 4 launches carry the P=A^16 squaring chain as a fused segment.
    gatherBu<<<ROWS_, 256>>>(Bu, FA + AP);
    float* cur = FA; float* nxt = FB;
    for (int j = 1; j < CH_; j++) {
        GA s = mkGA(cur + AP, HD_, Amat, nxt + AP, HD_, HD_, GF_SADD,
                    nullptr, Bu, nullptr, nullptr, j);
        if (j == 1)
            gemm_two<<<dim3(8, 48), 128>>>(s, mkGA(Amat, HD_, Amat, P0, HD_, HD_, 0), 32); // A^2
        else if (j == 2)
            gemm_two<<<dim3(8, 48), 128>>>(s, mkGA(P0, HD_, P0, P1, HD_, HD_, 0), 32);     // A^4
        else if (j == 3)
            gemm_two<<<dim3(8, 48), 128>>>(s, mkGA(P1, HD_, P1, P0, HD_, HD_, 0), 32);     // A^8
        else if (j == 4)
            gemm_two<<<dim3(8, 48), 128>>>(s, mkGA(P0, HD_, P0, P1, HD_, HD_, 0), 32);     // A^16
        else
            gemm_one<<<dim3(8, 32), 128>>>(s);
        float* t = cur; cur = nxt; nxt = t;
    }
    // local endpoints F in cur; P = A^16 in P1

    // 5) Hillis-Steele inclusive prefix over 128 chunks (7 rounds):
    //    F'_c = F_{c-s} @ P^s + F_c; apron supplies zeros. Each round (but the
    //    last) fuses the squaring producing P^(2s) for the next round.
    float* Pk = P1; float* Po = P0;
    for (int r = 0; r < 7; r++) {
        const int s = 1 << r;
        GA pre = mkGA(cur + AP - (size_t)16 * s * HD_, HD_, Pk, nxt + AP,
                      HD_, HD_, GF_ADDM, nullptr, nullptr, nullptr, cur + AP);
        if (r < 6) {
            gemm_two<<<dim3(8, 48), 128>>>(pre, mkGA(Pk, HD_, Pk, Po, HD_, HD_, 0), 32);
            float* u = Pk; Pk = Po; Po = u;
        } else {
            gemm_one<<<dim3(8, 32), 128>>>(pre);
        }
        float* t = cur; cur = nxt; nxt = t;
    }
    // inclusive prefix in cur; exclusive prefix = 16 rows back

    // 6) Phase 2: true recurrence per chunk from carry-in; scatter to d_out
    for (int j = 0; j < CH_; j++) {
        const float* Ain = (j == 0) ? (cur + AP - (size_t)16 * HD_) : (cur + AP);
        gemm_one<<<dim3(8, 32), 128>>>(mkGA(Ain, HD_, Amat, nxt + AP, HD_, HD_,
                                            GF_SADD | GF_SSTORE,
                                            nullptr, Bu, outH, nullptr, j));
        float* t = cur; cur = nxt; nxt = t;
    }

    // 7) z = x[:, -1, :] @ W_res + b_res + H_seq_pre[:, -1, :]
    sgemm16<SF_BIAS | SF_ADD><<<16, 256>>>(x + (size_t)(SEQ_ - 1) * LIN_,
                                           (long)SEQ_ * LIN_,
                                           Wres, HD_, Z, HD_, bres,
                                           outH + (size_t)(SEQ_ - 1) * HD_,
                                           (long)SEQ_ * HD_, BATCH_, LIN_);
    // 8) LayerNorm
    ln16<<<BATCH_, 256>>>(Z, lng, lnb, HL);
    // 9) MLP head
    sgemm16<SF_BIAS | SF_RELU><<<FMLP_ / 64, 256>>>(HL, HD_, W1, FMLP_, T, FMLP_,
                                                    b1, nullptr, 0, BATCH_, HD_);
    sgemm16<SF_BIAS><<<HD_ / 64, 256>>>(T, FMLP_, W2, HD_, out0, HD_,
                                        b2, nullptr, 0, BATCH_, FMLP_);
}

// round 12
// speedup vs baseline: 1.1244x; 1.1244x over previous
#include <cuda_runtime.h>
#include <cstdint>

#define BATCH_ 16
#define SEQ_   2048
#define LIN_   256
#define MENC_  512
#define HD_    1024
#define FMLP_  4096
#define CH_    16
#define NCH_   128
#define ROWS_  (NCH_*BATCH_)        // 2048
#define APRON_ 1024
#define FROWS_ (APRON_ + ROWS_)     // 3072

// ---------- scratch (device globals; allocation is forbidden) ----------
__device__ float g_Wx[LIN_*HD_];
__device__ float g_bvec[HD_];
__device__ float g_Bu[(size_t)BATCH_*SEQ_*HD_];
__device__ float g_P0[HD_*HD_];
__device__ float g_P1[HD_*HD_];
__device__ float g_FA[(size_t)FROWS_*HD_];
__device__ float g_FB[(size_t)FROWS_*HD_];
__device__ float g_Z [BATCH_*HD_];
__device__ float g_HL[BATCH_*HD_];
__device__ float g_T [BATCH_*FMLP_];

#define GF_BIAS   1
#define GF_SADD   2
#define GF_SSTORE 4
#define GF_ADDM   8

struct GA {
    const float* A; const float* B; float* C;
    const float* bias; const float* scanB; float* scanO; const float* addM;
    int lda, N, K, jstep, flags;
};

static inline GA mkGA(const float* A, int lda, const float* B, float* C,
                      int N, int K, int flags,
                      const float* bias = nullptr,
                      const float* scanB = nullptr, float* scanO = nullptr,
                      const float* addM = nullptr, int jstep = 0)
{
    GA g; g.A = A; g.B = B; g.C = C; g.bias = bias; g.scanB = scanB;
    g.scanO = scanO; g.addM = addM; g.lda = lda; g.N = N; g.K = K;
    g.jstep = jstep; g.flags = flags; return g;
}

// 128(m) x 128(n) tile, 256 threads (8 warps -> 2/SMSP), 8x8 micro-tile,
// packed f32x2 FMA. A-pairs along m come straight from LDS.128 of the
// k-major transposed A tile; 2 B/FFMA2 smem economy.
__device__ __forceinline__ void gemm_core(const GA& g,
                                          float (&As)[2][16][132],
                                          float (&Bs)[2][16][132],
                                          int bxi, int byi)
{
    const int tid = threadIdx.x;
    const int tm = tid >> 4, tn = tid & 15;
    const int m0 = byi * 128, n0 = bxi * 128;
    const int lar = tid >> 1, lac = (tid & 1) * 8;
    const int lbr = tid >> 4, lbc = (tid & 15) * 8;
    const int N = g.N, K = g.K;

    const float* Aload = g.A + (size_t)(m0 + lar) * g.lda + lac;
    const float* Bload = g.B + (size_t)lbr * N + n0 + lbc;

    unsigned long long acc[4][8];
#pragma unroll
    for (int p = 0; p < 4; p++)
#pragma unroll
        for (int q = 0; q < 8; q++) acc[p][q] = 0ull;

    float4 a0 = *(const float4*)(Aload);
    float4 a1 = *(const float4*)(Aload + 4);
    float4 b0 = *(const float4*)(Bload);
    float4 b1 = *(const float4*)(Bload + 4);
    As[0][lac+0][lar]=a0.x; As[0][lac+1][lar]=a0.y; As[0][lac+2][lar]=a0.z; As[0][lac+3][lar]=a0.w;
    As[0][lac+4][lar]=a1.x; As[0][lac+5][lar]=a1.y; As[0][lac+6][lar]=a1.z; As[0][lac+7][lar]=a1.w;
    *(float4*)&Bs[0][lbr][lbc]     = b0;
    *(float4*)&Bs[0][lbr][lbc + 4] = b1;
    __syncthreads();

    int buf = 0;
    for (int kt = 0; kt < K; kt += 16) {
        const bool more = (kt + 16) < K;
        if (more) {
            a0 = *(const float4*)(Aload + kt + 16);
            a1 = *(const float4*)(Aload + kt + 20);
            const float* Bk = Bload + (size_t)(kt + 16) * N;
            b0 = *(const float4*)(Bk);
            b1 = *(const float4*)(Bk + 4);
        }
#pragma unroll
        for (int k = 0; k < 16; k++) {
            const ulonglong2 pa0 = *(const ulonglong2*)&As[buf][k][tm * 8];
            const ulonglong2 pa1 = *(const ulonglong2*)&As[buf][k][tm * 8 + 4];
            const float4 x = *(const float4*)&Bs[buf][k][tn * 8];
            const float4 y = *(const float4*)&Bs[buf][k][tn * 8 + 4];
            unsigned long long pb[8];
            asm("mov.b64 %0,{%1,%1};" : "=l"(pb[0]) : "f"(x.x));
            asm("mov.b64 %0,{%1,%1};" : "=l"(pb[1]) : "f"(x.y));
            asm("mov.b64 %0,{%1,%1};" : "=l"(pb[2]) : "f"(x.z));
            asm("mov.b64 %0,{%1,%1};" : "=l"(pb[3]) : "f"(x.w));
            asm("mov.b64 %0,{%1,%1};" : "=l"(pb[4]) : "f"(y.x));
            asm("mov.b64 %0,{%1,%1};" : "=l"(pb[5]) : "f"(y.y));
            asm("mov.b64 %0,{%1,%1};" : "=l"(pb[6]) : "f"(y.z));
            asm("mov.b64 %0,{%1,%1};" : "=l"(pb[7]) : "f"(y.w));
#pragma unroll
            for (int q = 0; q < 8; q++) {
                asm("fma.rn.f32x2 %0,%1,%2,%0;" : "+l"(acc[0][q]) : "l"(pa0.x), "l"(pb[q]));
                asm("fma.rn.f32x2 %0,%1,%2,%0;" : "+l"(acc[1][q]) : "l"(pa0.y), "l"(pb[q]));
                asm("fma.rn.f32x2 %0,%1,%2,%0;" : "+l"(acc[2][q]) : "l"(pa1.x), "l"(pb[q]));
                asm("fma.rn.f32x2 %0,%1,%2,%0;" : "+l"(acc[3][q]) : "l"(pa1.y), "l"(pb[q]));
            }
        }
        if (more) {
            const int nb = buf ^ 1;
            As[nb][lac+0][lar]=a0.x; As[nb][lac+1][lar]=a0.y; As[nb][lac+2][lar]=a0.z; As[nb][lac+3][lar]=a0.w;
            As[nb][lac+4][lar]=a1.x; As[nb][lac+5][lar]=a1.y; As[nb][lac+6][lar]=a1.z; As[nb][lac+7][lar]=a1.w;
            *(float4*)&Bs[nb][lbr][lbc]     = b0;
            *(float4*)&Bs[nb][lbr][lbc + 4] = b1;
            __syncthreads();
        }
        buf ^= 1;
    }

    float cv[8][8];
#pragma unroll
    for (int p = 0; p < 4; p++)
#pragma unroll
        for (int q = 0; q < 8; q++)
            asm("mov.b64 {%0,%1},%2;"
                : "=f"(cv[2*p][q]), "=f"(cv[2*p+1][q]) : "l"(acc[p][q]));

    const int F = g.flags;
    const int gc = n0 + tn * 8;
    float4 bv0 = make_float4(0.f,0.f,0.f,0.f), bv1 = bv0;
    if (F & GF_BIAS) {
        bv0 = *(const float4*)(g.bias + gc);
        bv1 = *(const float4*)(g.bias + gc + 4);
    }
#pragma unroll
    for (int mr = 0; mr < 8; mr++) {
        const int gm = m0 + tm * 8 + mr;
        float4 v0 = make_float4(cv[mr][0], cv[mr][1], cv[mr][2], cv[mr][3]);
        float4 v1 = make_float4(cv[mr][4], cv[mr][5], cv[mr][6], cv[mr][7]);
        if (F & GF_BIAS) {
            v0.x += bv0.x; v0.y += bv0.y; v0.z += bv0.z; v0.w += bv0.w;
            v1.x += bv1.x; v1.y += bv1.y; v1.z += bv1.z; v1.w += bv1.w;
        }
        if (F & GF_ADDM) {
            float4 u0 = *(const float4*)(g.addM + (size_t)gm * N + gc);
            float4 u1 = *(const float4*)(g.addM + (size_t)gm * N + gc + 4);
            v0.x += u0.x; v0.y += u0.y; v0.z += u0.z; v0.w += u0.w;
            v1.x += u1.x; v1.y += u1.y; v1.z += u1.z; v1.w += u1.w;
        }
        size_t soff = 0;
        if (F & (GF_SADD | GF_SSTORE))
            soff = ((size_t)(gm & 15) * SEQ_ + (size_t)(gm >> 4) * CH_ + g.jstep) * HD_ + gc;
        if (F & GF_SADD) {
            float4 s0 = *(const float4*)(g.scanB + soff);
            float4 s1 = *(const float4*)(g.scanB + soff + 4);
            v0.x += s0.x; v0.y += s0.y; v0.z += s0.z; v0.w += s0.w;
            v1.x += s1.x; v1.y += s1.y; v1.z += s1.z; v1.w += s1.w;
        }
        *(float4*)(g.C + (size_t)gm * N + gc)     = v0;
        *(float4*)(g.C + (size_t)gm * N + gc + 4) = v1;
        if (F & GF_SSTORE) {
            *(float4*)(g.scanO + soff)     = v0;
            *(float4*)(g.scanO + soff + 4) = v1;
        }
    }
}

__global__ void __launch_bounds__(256) gemm_one(GA g)
{
    __shared__ float As[2][16][132];
    __shared__ float Bs[2][16][132];
    gemm_core(g, As, Bs, blockIdx.x, blockIdx.y);
}

// Two independent GEMM segments in one launch (split on blockIdx.y):
// hides the serial P-squaring chain behind the scan/prefix steps.
__global__ void __launch_bounds__(256) gemm_two(GA g1, GA g2, int bySplit)
{
    __shared__ float As[2][16][132];
    __shared__ float Bs[2][16][132];
    if ((int)blockIdx.y < bySplit)
        gemm_core(g1, As, Bs, blockIdx.x, blockIdx.y);
    else
        gemm_core(g2, As, Bs, blockIdx.x, blockIdx.y - bySplit);
}

#define SF_BIAS 1
#define SF_RELU 2
#define SF_ADD  4

// Small-M (<=16) GEMM: per block 16 rows x 64 cols, 256 threads.
template<int F>
__global__ void __launch_bounds__(256)
sgemm16(const float* __restrict__ Ap, long lda,
        const float* __restrict__ Bp, int ldb,
        float* __restrict__ Cp, int ldc,
        const float* __restrict__ bias,
        const float* __restrict__ addend, long ldadd,
        int M, int K)
{
    __shared__ float As[16][33];
    const int tid = threadIdx.x;
    const int c = tid & 63, g = tid >> 6;
    const int col = blockIdx.x * 64 + c;
    float acc[4] = {0.f, 0.f, 0.f, 0.f};
    for (int k0 = 0; k0 < K; k0 += 32) {
        __syncthreads();
        for (int e = tid; e < 512; e += 256) {
            const int r = e >> 5, kk = e & 31;
            As[r][kk] = (r < M) ? Ap[(size_t)r * lda + k0 + kk] : 0.f;
        }
        __syncthreads();
#pragma unroll 8
        for (int kk = 0; kk < 32; kk++) {
            const float bv = Bp[(size_t)(k0 + kk) * ldb + col];
#pragma unroll
            for (int i = 0; i < 4; i++) acc[i] += As[g * 4 + i][kk] * bv;
        }
    }
#pragma unroll
    for (int i = 0; i < 4; i++) {
        const int r = g * 4 + i;
        if (r < M) {
            float v = acc[i];
            if (F & SF_BIAS) v += bias[col];
            if (F & SF_ADD)  v += addend[(size_t)r * ldadd + col];
            if (F & SF_RELU) v = fmaxf(v, 0.f);
            Cp[(size_t)r * ldc + col] = v;
        }
    }
}

__global__ void __launch_bounds__(256)
ln16(const float* __restrict__ z, const float* __restrict__ gam,
     const float* __restrict__ bet, float* __restrict__ o)
{
    __shared__ float s1[8], s2[8];
    const int b = blockIdx.x, tid = threadIdx.x;
    float4 v = ((const float4*)(z + (size_t)b * HD_))[tid];
    float s = v.x + v.y + v.z + v.w;
    float q = v.x*v.x + v.y*v.y + v.z*v.z + v.w*v.w;
    for (int d = 16; d > 0; d >>= 1) {
        s += __shfl_xor_sync(0xffffffffu, s, d);
        q += __shfl_xor_sync(0xffffffffu, q, d);
    }
    if ((tid & 31) == 0) { s1[tid >> 5] = s; s2[tid >> 5] = q; }
    __syncthreads();
    if (tid < 8) {
        s = s1[tid]; q = s2[tid];
        for (int d = 4; d > 0; d >>= 1) {
            s += __shfl_xor_sync(0xffu, s, d);
            q += __shfl_xor_sync(0xffu, q, d);
        }
        if (tid == 0) { s1[0] = s; s2[0] = q; }
    }
    __syncthreads();
    const float mu = s1[0] * (1.f / HD_);
    const float var = s2[0] * (1.f / HD_) - mu * mu;
    const float rs = rsqrtf(var + 1e-5f);
    float4 gg = ((const float4*)gam)[tid];
    float4 bb = ((const float4*)bet)[tid];
    float4 r;
    r.x = (v.x - mu) * rs * gg.x + bb.x;
    r.y = (v.y - mu) * rs * gg.y + bb.y;
    r.z = (v.z - mu) * rs * gg.z + bb.z;
    r.w = (v.w - mu) * rs * gg.w + bb.w;
    ((float4*)(o + (size_t)b * HD_))[tid] = r;
}

// phase-1 init: local state at j=0 is Bu[b, c*CH, :]
__global__ void gatherBu(const float* __restrict__ Bu, float* __restrict__ H)
{
    const int r = blockIdx.x;
    const size_t src = ((size_t)(r & 15) * SEQ_ + (size_t)(r >> 4) * CH_) * HD_;
    ((float4*)(H + (size_t)r * HD_))[threadIdx.x] =
        ((const float4*)(Bu + src))[threadIdx.x];
}

__global__ void zero4(float* p)
{
    ((float4*)p)[(size_t)blockIdx.x * 256 + threadIdx.x] = make_float4(0.f, 0.f, 0.f, 0.f);
}

extern "C" void kernel_launch(void* const* d_in, const int* in_sizes, int n_in,
                              void* d_out, int out_size)
{
    (void)in_sizes; (void)n_in; (void)out_size;
    const float* x    = (const float*)d_in[0];
    const float* Wenc = (const float*)d_in[1];
    const float* benc = (const float*)d_in[2];
    const float* WB   = (const float*)d_in[3];
    const float* Amat = (const float*)d_in[4];
    const float* Wres = (const float*)d_in[5];
    const float* bres = (const float*)d_in[6];
    const float* lng  = (const float*)d_in[7];
    const float* lnb  = (const float*)d_in[8];
    const float* W1   = (const float*)d_in[9];
    const float* b1   = (const float*)d_in[10];
    const float* W2   = (const float*)d_in[11];
    const float* b2   = (const float*)d_in[12];
    float* out0 = (float*)d_out;                 // (16,1024) MLP head
    float* outH = out0 + BATCH_ * HD_;           // (16,2048,1024) H_seq_pre

    float *Wx, *bvec, *Bu, *P0, *P1, *FA, *FB, *Z, *HL, *T;
    cudaGetSymbolAddress((void**)&Wx,   g_Wx);
    cudaGetSymbolAddress((void**)&bvec, g_bvec);
    cudaGetSymbolAddress((void**)&Bu,   g_Bu);
    cudaGetSymbolAddress((void**)&P0,   g_P0);
    cudaGetSymbolAddress((void**)&P1,   g_P1);
    cudaGetSymbolAddress((void**)&FA,   g_FA);
    cudaGetSymbolAddress((void**)&FB,   g_FB);
    cudaGetSymbolAddress((void**)&Z,    g_Z);
    cudaGetSymbolAddress((void**)&HL,   g_HL);
    cudaGetSymbolAddress((void**)&T,    g_T);

    const size_t AP = (size_t)APRON_ * HD_;

    // 1) Wx = W_enc @ W_B ; bvec = b_enc @ W_B
    gemm_one<<<dim3(8, 4), 256>>>(mkGA(Wenc, MENC_, WB, Wx, HD_, MENC_, 0));
    sgemm16<0><<<16, 256>>>(benc, MENC_, WB, HD_, bvec, HD_,
                            nullptr, nullptr, 0, 1, MENC_);

    // 2) Bu = x2d @ Wx + bvec   (32768 x 1024, K=256)
    gemm_one<<<dim3(8, 256), 256>>>(mkGA(x, LIN_, Wx, Bu, HD_, LIN_, GF_BIAS, bvec));

    // 3) zero aprons (1024 rows each buffer)
    zero4<<<1024, 256>>>(FA);
    zero4<<<1024, 256>>>(FB);

    // 4) Phase 1: local scans from zero (15 serial steps, M=2048).
    //    First 4 launches carry the P=A^16 squaring chain as a fused segment.
    gatherBu<<<ROWS_, 256>>>(Bu, FA + AP);
    float* cur = FA; float* nxt = FB;
    for (int j = 1; j < CH_; j++) {
        GA s = mkGA(cur + AP, HD_, Amat, nxt + AP, HD_, HD_, GF_SADD,
                    nullptr, Bu, nullptr, nullptr, j);
        if (j == 1)
            gemm_two<<<dim3(8, 24), 256>>>(s, mkGA(Amat, HD_, Amat, P0, HD_, HD_, 0), 16); // A^2
        else if (j == 2)
            gemm_two<<<dim3(8, 24), 256>>>(s, mkGA(P0, HD_, P0, P1, HD_, HD_, 0), 16);     // A^4
        else if (j == 3)
            gemm_two<<<dim3(8, 24), 256>>>(s, mkGA(P1, HD_, P1, P0, HD_, HD_, 0), 16);     // A^8
        else if (j == 4)
            gemm_two<<<dim3(8, 24), 256>>>(s, mkGA(P0, HD_, P0, P1, HD_, HD_, 0), 16);     // A^16
        else
            gemm_one<<<dim3(8, 16), 256>>>(s);
        float* t = cur; cur = nxt; nxt = t;
    }
    // local endpoints F in cur; P = A^16 in P1

    // 5) Hillis-Steele inclusive prefix over 128 chunks (7 rounds):
    //    F'_c = F_{c-s} @ P^s + F_c; apron supplies zeros. Each round (but the
    //    last) fuses the squaring producing P^(2s) for the next round.
    float* Pk = P1; float* Po = P0;
    for (int r = 0; r < 7; r++) {
        const int s = 1 << r;
        GA pre = mkGA(cur + AP - (size_t)16 * s * HD_, HD_, Pk, nxt + AP,
                      HD_, HD_, GF_ADDM, nullptr, nullptr, nullptr, cur + AP);
        if (r < 6) {
            gemm_two<<<dim3(8, 24), 256>>>(pre, mkGA(Pk, HD_, Pk, Po, HD_, HD_, 0), 16);
            float* u = Pk; Pk = Po; Po = u;
        } else {
            gemm_one<<<dim3(8, 16), 256>>>(pre);
        }
        float* t = cur; cur = nxt; nxt = t;
    }
    // inclusive prefix in cur; exclusive prefix = 16 rows back

    // 6) Phase 2: true recurrence per chunk from carry-in; scatter to d_out
    for (int j = 0; j < CH_; j++) {
        const float* Ain = (j == 0) ? (cur + AP - (size_t)16 * HD_) : (cur + AP);
        gemm_one<<<dim3(8, 16), 256>>>(mkGA(Ain, HD_, Amat, nxt + AP, HD_, HD_,
                                            GF_SADD | GF_SSTORE,
                                            nullptr, Bu, outH, nullptr, j));
        float* t = cur; cur = nxt; nxt = t;
    }

    // 7) z = x[:, -1, :] @ W_res + b_res + H_seq_pre[:, -1, :]
    sgemm16<SF_BIAS | SF_ADD><<<16, 256>>>(x + (size_t)(SEQ_ - 1) * LIN_,
                                           (long)SEQ_ * LIN_,
                                           Wres, HD_, Z, HD_, bres,
                                           outH + (size_t)(SEQ_ - 1) * HD_,
                                           (long)SEQ_ * HD_, BATCH_, LIN_);
    // 8) LayerNorm
    ln16<<<BATCH_, 256>>>(Z, lng, lnb, HL);
    // 9) MLP head
    sgemm16<SF_BIAS | SF_RELU><<<FMLP_ / 64, 256>>>(HL, HD_, W1, FMLP_, T, FMLP_,
                                                    b1, nullptr, 0, BATCH_, HD_);
    sgemm16<SF_BIAS><<<HD_ / 64, 256>>>(T, FMLP_, W2, HD_, out0, HD_,
                                        b2, nullptr, 0, BATCH_, FMLP_);
}

// round 13
// speedup vs baseline: 1.1481x; 1.0211x over previous
#include <cuda_runtime.h>
#include <cstdint>

#define BATCH_ 16
#define SEQ_   2048
#define LIN_   256
#define MENC_  512
#define HD_    1024
#define FMLP_  4096
#define CH_    16
#define NCH_   128
#define ROWS_  (NCH_*BATCH_)        // 2048
#define APRON_ 1024
#define FROWS_ (APRON_ + ROWS_)     // 3072

// ---------- scratch (device globals; allocation is forbidden) ----------
__device__ float g_Wx[LIN_*HD_];
__device__ float g_bvec[HD_];
__device__ float g_Bu[(size_t)BATCH_*SEQ_*HD_];
__device__ float g_P0[HD_*HD_];
__device__ float g_P1[HD_*HD_];
__device__ float g_FA[(size_t)FROWS_*HD_];
__device__ float g_FB[(size_t)FROWS_*HD_];
__device__ float g_Z [BATCH_*HD_];
__device__ float g_HL[BATCH_*HD_];
__device__ float g_T [BATCH_*FMLP_];

#define GF_BIAS   1
#define GF_SADD   2
#define GF_SSTORE 4
#define GF_ADDM   8

struct GA {
    const float* A; const float* B; float* C;
    const float* bias; const float* scanB; float* scanO; const float* addM;
    int lda, N, K, jstep, flags;
};

static inline GA mkGA(const float* A, int lda, const float* B, float* C,
                      int N, int K, int flags,
                      const float* bias = nullptr,
                      const float* scanB = nullptr, float* scanO = nullptr,
                      const float* addM = nullptr, int jstep = 0)
{
    GA g; g.A = A; g.B = B; g.C = C; g.bias = bias; g.scanB = scanB;
    g.scanO = scanO; g.addM = addM; g.lda = lda; g.N = N; g.K = K;
    g.jstep = jstep; g.flags = flags; return g;
}

__device__ __forceinline__ uint32_t s2u(const void* p){
    uint32_t a; asm("{ .reg .u64 t; cvta.to.shared.u64 t,%1; cvt.u32.u64 %0,t; }" : "=r"(a) : "l"(p));
    return a;
}
__device__ __forceinline__ void cpasync16(uint32_t dst, const float* src){
    asm volatile("cp.async.cg.shared.global [%0],[%1],16;" :: "r"(dst), "l"(src));
}
#define CP_COMMIT() asm volatile("cp.async.commit_group;" ::: "memory")
#define CP_WAIT0()  asm volatile("cp.async.wait_group 0;" ::: "memory")

// 128(m) x 128(n) tile, 256 threads (8 warps), 8x8 micro-tile, packed f32x2
// FMA. A: register-staged transpose to k-major smem (pairs along m feed
// FFMA2 from LDS.128 directly). B: cp.async bulk copies (layout matches
// global), double-buffered, ONE __syncthreads per 16-k panel.
__device__ __forceinline__ void gemm_core(const GA& g,
                                          float (&As)[2][16][132],
                                          float (&Bs)[2][16][132],
                                          int bxi, int byi)
{
    const int tid = threadIdx.x;
    const int tm = tid >> 4, tn = tid & 15;
    const int m0 = byi * 128, n0 = bxi * 128;
    const int lar = tid >> 1, lac = (tid & 1) * 8;
    const int N = g.N, K = g.K;

    const float* Aload = g.A + (size_t)(m0 + lar) * g.lda + lac;
    const float* Bload = g.B + n0;
    const uint32_t bsU = s2u(&Bs[0][0][0]);
    const int br = tid >> 5, bc = (tid & 31) * 4;   // 16 k-rows x 32 float4

    unsigned long long acc[4][8];
#pragma unroll
    for (int p = 0; p < 4; p++)
#pragma unroll
        for (int q = 0; q < 8; q++) acc[p][q] = 0ull;

    // prologue: panel 0
    {
        cpasync16(bsU + ((br * 132 + bc) << 2),       Bload + (size_t)br * N + bc);
        cpasync16(bsU + (((br + 8) * 132 + bc) << 2), Bload + (size_t)(br + 8) * N + bc);
        CP_COMMIT();
        float4 a0 = *(const float4*)(Aload);
        float4 a1 = *(const float4*)(Aload + 4);
        As[0][lac+0][lar]=a0.x; As[0][lac+1][lar]=a0.y; As[0][lac+2][lar]=a0.z; As[0][lac+3][lar]=a0.w;
        As[0][lac+4][lar]=a1.x; As[0][lac+5][lar]=a1.y; As[0][lac+6][lar]=a1.z; As[0][lac+7][lar]=a1.w;
    }

    int buf = 0;
    for (int kt = 0; kt < K; kt += 16) {
        const bool more = (kt + 16) < K;
        CP_WAIT0();
        __syncthreads();            // panel kt visible to all; prior buffer free
        if (more) {
            const float* Bk = Bload + (size_t)(kt + 16) * N;
            const uint32_t bb = bsU + (uint32_t)((buf ^ 1) * 16 * 132 * 4);
            cpasync16(bb + ((br * 132 + bc) << 2),       Bk + (size_t)br * N + bc);
            cpasync16(bb + (((br + 8) * 132 + bc) << 2), Bk + (size_t)(br + 8) * N + bc);
            CP_COMMIT();
        }
        float4 a0, a1;
        if (more) {
            a0 = *(const float4*)(Aload + kt + 16);
            a1 = *(const float4*)(Aload + kt + 20);
        }
#pragma unroll
        for (int k = 0; k < 16; k++) {
            const ulonglong2 pa0 = *(const ulonglong2*)&As[buf][k][tm * 8];
            const ulonglong2 pa1 = *(const ulonglong2*)&As[buf][k][tm * 8 + 4];
            const float4 x = *(const float4*)&Bs[buf][k][tn * 8];
            const float4 y = *(const float4*)&Bs[buf][k][tn * 8 + 4];
            unsigned long long pb[8];
            asm("mov.b64 %0,{%1,%1};" : "=l"(pb[0]) : "f"(x.x));
            asm("mov.b64 %0,{%1,%1};" : "=l"(pb[1]) : "f"(x.y));
            asm("mov.b64 %0,{%1,%1};" : "=l"(pb[2]) : "f"(x.z));
            asm("mov.b64 %0,{%1,%1};" : "=l"(pb[3]) : "f"(x.w));
            asm("mov.b64 %0,{%1,%1};" : "=l"(pb[4]) : "f"(y.x));
            asm("mov.b64 %0,{%1,%1};" : "=l"(pb[5]) : "f"(y.y));
            asm("mov.b64 %0,{%1,%1};" : "=l"(pb[6]) : "f"(y.z));
            asm("mov.b64 %0,{%1,%1};" : "=l"(pb[7]) : "f"(y.w));
#pragma unroll
            for (int q = 0; q < 8; q++) {
                asm("fma.rn.f32x2 %0,%1,%2,%0;" : "+l"(acc[0][q]) : "l"(pa0.x), "l"(pb[q]));
                asm("fma.rn.f32x2 %0,%1,%2,%0;" : "+l"(acc[1][q]) : "l"(pa0.y), "l"(pb[q]));
                asm("fma.rn.f32x2 %0,%1,%2,%0;" : "+l"(acc[2][q]) : "l"(pa1.x), "l"(pb[q]));
                asm("fma.rn.f32x2 %0,%1,%2,%0;" : "+l"(acc[3][q]) : "l"(pa1.y), "l"(pb[q]));
            }
        }
        if (more) {
            const int nb = buf ^ 1;
            As[nb][lac+0][lar]=a0.x; As[nb][lac+1][lar]=a0.y; As[nb][lac+2][lar]=a0.z; As[nb][lac+3][lar]=a0.w;
            As[nb][lac+4][lar]=a1.x; As[nb][lac+5][lar]=a1.y; As[nb][lac+6][lar]=a1.z; As[nb][lac+7][lar]=a1.w;
        }
        buf ^= 1;
    }

    float cv[8][8];
#pragma unroll
    for (int p = 0; p < 4; p++)
#pragma unroll
        for (int q = 0; q < 8; q++)
            asm("mov.b64 {%0,%1},%2;"
                : "=f"(cv[2*p][q]), "=f"(cv[2*p+1][q]) : "l"(acc[p][q]));

    const int F = g.flags;
    const int gc = n0 + tn * 8;
    float4 bv0 = make_float4(0.f,0.f,0.f,0.f), bv1 = bv0;
    if (F & GF_BIAS) {
        bv0 = *(const float4*)(g.bias + gc);
        bv1 = *(const float4*)(g.bias + gc + 4);
    }
#pragma unroll
    for (int mr = 0; mr < 8; mr++) {
        const int gm = m0 + tm * 8 + mr;
        float4 v0 = make_float4(cv[mr][0], cv[mr][1], cv[mr][2], cv[mr][3]);
        float4 v1 = make_float4(cv[mr][4], cv[mr][5], cv[mr][6], cv[mr][7]);
        if (F & GF_BIAS) {
            v0.x += bv0.x; v0.y += bv0.y; v0.z += bv0.z; v0.w += bv0.w;
            v1.x += bv1.x; v1.y += bv1.y; v1.z += bv1.z; v1.w += bv1.w;
        }
        if (F & GF_ADDM) {
            float4 u0 = *(const float4*)(g.addM + (size_t)gm * N + gc);
            float4 u1 = *(const float4*)(g.addM + (size_t)gm * N + gc + 4);
            v0.x += u0.x; v0.y += u0.y; v0.z += u0.z; v0.w += u0.w;
            v1.x += u1.x; v1.y += u1.y; v1.z += u1.z; v1.w += u1.w;
        }
        size_t soff = 0;
        if (F & (GF_SADD | GF_SSTORE))
            soff = ((size_t)(gm & 15) * SEQ_ + (size_t)(gm >> 4) * CH_ + g.jstep) * HD_ + gc;
        if (F & GF_SADD) {
            float4 s0 = *(const float4*)(g.scanB + soff);
            float4 s1 = *(const float4*)(g.scanB + soff + 4);
            v0.x += s0.x; v0.y += s0.y; v0.z += s0.z; v0.w += s0.w;
            v1.x += s1.x; v1.y += s1.y; v1.z += s1.z; v1.w += s1.w;
        }
        *(float4*)(g.C + (size_t)gm * N + gc)     = v0;
        *(float4*)(g.C + (size_t)gm * N + gc + 4) = v1;
        if (F & GF_SSTORE) {
            *(float4*)(g.scanO + soff)     = v0;
            *(float4*)(g.scanO + soff + 4) = v1;
        }
    }
}

__global__ void __launch_bounds__(256, 2) gemm_one(GA g)
{
    __shared__ float As[2][16][132];
    __shared__ float Bs[2][16][132];
    gemm_core(g, As, Bs, blockIdx.x, blockIdx.y);
}

// Two independent GEMM segments in one launch (split on blockIdx.y):
// hides the serial P-squaring chain behind the scan/prefix steps.
__global__ void __launch_bounds__(256, 2) gemm_two(GA g1, GA g2, int bySplit)
{
    __shared__ float As[2][16][132];
    __shared__ float Bs[2][16][132];
    if ((int)blockIdx.y < bySplit)
        gemm_core(g1, As, Bs, blockIdx.x, blockIdx.y);
    else
        gemm_core(g2, As, Bs, blockIdx.x, blockIdx.y - bySplit);
}

#define SF_BIAS 1
#define SF_RELU 2
#define SF_ADD  4

// Small-M (<=16) GEMM: per block 16 rows x 64 cols, 256 threads.
template<int F>
__global__ void __launch_bounds__(256)
sgemm16(const float* __restrict__ Ap, long lda,
        const float* __restrict__ Bp, int ldb,
        float* __restrict__ Cp, int ldc,
        const float* __restrict__ bias,
        const float* __restrict__ addend, long ldadd,
        int M, int K)
{
    __shared__ float As[16][33];
    const int tid = threadIdx.x;
    const int c = tid & 63, g = tid >> 6;
    const int col = blockIdx.x * 64 + c;
    float acc[4] = {0.f, 0.f, 0.f, 0.f};
    for (int k0 = 0; k0 < K; k0 += 32) {
        __syncthreads();
        for (int e = tid; e < 512; e += 256) {
            const int r = e >> 5, kk = e & 31;
            As[r][kk] = (r < M) ? Ap[(size_t)r * lda + k0 + kk] : 0.f;
        }
        __syncthreads();
#pragma unroll 8
        for (int kk = 0; kk < 32; kk++) {
            const float bv = Bp[(size_t)(k0 + kk) * ldb + col];
#pragma unroll
            for (int i = 0; i < 4; i++) acc[i] += As[g * 4 + i][kk] * bv;
        }
    }
#pragma unroll
    for (int i = 0; i < 4; i++) {
        const int r = g * 4 + i;
        if (r < M) {
            float v = acc[i];
            if (F & SF_BIAS) v += bias[col];
            if (F & SF_ADD)  v += addend[(size_t)r * ldadd + col];
            if (F & SF_RELU) v = fmaxf(v, 0.f);
            Cp[(size_t)r * ldc + col] = v;
        }
    }
}

__global__ void __launch_bounds__(256)
ln16(const float* __restrict__ z, const float* __restrict__ gam,
     const float* __restrict__ bet, float* __restrict__ o)
{
    __shared__ float s1[8], s2[8];
    const int b = blockIdx.x, tid = threadIdx.x;
    float4 v = ((const float4*)(z + (size_t)b * HD_))[tid];
    float s = v.x + v.y + v.z + v.w;
    float q = v.x*v.x + v.y*v.y + v.z*v.z + v.w*v.w;
    for (int d = 16; d > 0; d >>= 1) {
        s += __shfl_xor_sync(0xffffffffu, s, d);
        q += __shfl_xor_sync(0xffffffffu, q, d);
    }
    if ((tid & 31) == 0) { s1[tid >> 5] = s; s2[tid >> 5] = q; }
    __syncthreads();
    if (tid < 8) {
        s = s1[tid]; q = s2[tid];
        for (int d = 4; d > 0; d >>= 1) {
            s += __shfl_xor_sync(0xffu, s, d);
            q += __shfl_xor_sync(0xffu, q, d);
        }
        if (tid == 0) { s1[0] = s; s2[0] = q; }
    }
    __syncthreads();
    const float mu = s1[0] * (1.f / HD_);
    const float var = s2[0] * (1.f / HD_) - mu * mu;
    const float rs = rsqrtf(var + 1e-5f);
    float4 gg = ((const float4*)gam)[tid];
    float4 bb = ((const float4*)bet)[tid];
    float4 r;
    r.x = (v.x - mu) * rs * gg.x + bb.x;
    r.y = (v.y - mu) * rs * gg.y + bb.y;
    r.z = (v.z - mu) * rs * gg.z + bb.z;
    r.w = (v.w - mu) * rs * gg.w + bb.w;
    ((float4*)(o + (size_t)b * HD_))[tid] = r;
}

// phase-1 init: local state at j=0 is Bu[b, c*CH, :]
__global__ void gatherBu(const float* __restrict__ Bu, float* __restrict__ H)
{
    const int r = blockIdx.x;
    const size_t src = ((size_t)(r & 15) * SEQ_ + (size_t)(r >> 4) * CH_) * HD_;
    ((float4*)(H + (size_t)r * HD_))[threadIdx.x] =
        ((const float4*)(Bu + src))[threadIdx.x];
}

__global__ void zero4(float* p)
{
    ((float4*)p)[(size_t)blockIdx.x * 256 + threadIdx.x] = make_float4(0.f, 0.f, 0.f, 0.f);
}

extern "C" void kernel_launch(void* const* d_in, const int* in_sizes, int n_in,
                              void* d_out, int out_size)
{
    (void)in_sizes; (void)n_in; (void)out_size;
    const float* x    = (const float*)d_in[0];
    const float* Wenc = (const float*)d_in[1];
    const float* benc = (const float*)d_in[2];
    const float* WB   = (const float*)d_in[3];
    const float* Amat = (const float*)d_in[4];
    const float* Wres = (const float*)d_in[5];
    const float* bres = (const float*)d_in[6];
    const float* lng  = (const float*)d_in[7];
    const float* lnb  = (const float*)d_in[8];
    const float* W1   = (const float*)d_in[9];
    const float* b1   = (const float*)d_in[10];
    const float* W2   = (const float*)d_in[11];
    const float* b2   = (const float*)d_in[12];
    float* out0 = (float*)d_out;                 // (16,1024) MLP head
    float* outH = out0 + BATCH_ * HD_;           // (16,2048,1024) H_seq_pre

    float *Wx, *bvec, *Bu, *P0, *P1, *FA, *FB, *Z, *HL, *T;
    cudaGetSymbolAddress((void**)&Wx,   g_Wx);
    cudaGetSymbolAddress((void**)&bvec, g_bvec);
    cudaGetSymbolAddress((void**)&Bu,   g_Bu);
    cudaGetSymbolAddress((void**)&P0,   g_P0);
    cudaGetSymbolAddress((void**)&P1,   g_P1);
    cudaGetSymbolAddress((void**)&FA,   g_FA);
    cudaGetSymbolAddress((void**)&FB,   g_FB);
    cudaGetSymbolAddress((void**)&Z,    g_Z);
    cudaGetSymbolAddress((void**)&HL,   g_HL);
    cudaGetSymbolAddress((void**)&T,    g_T);

    const size_t AP = (size_t)APRON_ * HD_;

    // 1) Wx = W_enc @ W_B ; bvec = b_enc @ W_B
    gemm_one<<<dim3(8, 4), 256>>>(mkGA(Wenc, MENC_, WB, Wx, HD_, MENC_, 0));
    sgemm16<0><<<16, 256>>>(benc, MENC_, WB, HD_, bvec, HD_,
                            nullptr, nullptr, 0, 1, MENC_);

    // 2) Bu = x2d @ Wx + bvec   (32768 x 1024, K=256)
    gemm_one<<<dim3(8, 256), 256>>>(mkGA(x, LIN_, Wx, Bu, HD_, LIN_, GF_BIAS, bvec));

    // 3) zero aprons (1024 rows each buffer)
    zero4<<<1024, 256>>>(FA);
    zero4<<<1024, 256>>>(FB);

    // 4) Phase 1: local scans from zero (15 serial steps, M=2048).
    //    First 4 launches carry the P=A^16 squaring chain as a fused segment.
    gatherBu<<<ROWS_, 256>>>(Bu, FA + AP);
    float* cur = FA; float* nxt = FB;
    for (int j = 1; j < CH_; j++) {
        GA s = mkGA(cur + AP, HD_, Amat, nxt + AP, HD_, HD_, GF_SADD,
                    nullptr, Bu, nullptr, nullptr, j);
        if (j == 1)
            gemm_two<<<dim3(8, 24), 256>>>(s, mkGA(Amat, HD_, Amat, P0, HD_, HD_, 0), 16); // A^2
        else if (j == 2)
            gemm_two<<<dim3(8, 24), 256>>>(s, mkGA(P0, HD_, P0, P1, HD_, HD_, 0), 16);     // A^4
        else if (j == 3)
            gemm_two<<<dim3(8, 24), 256>>>(s, mkGA(P1, HD_, P1, P0, HD_, HD_, 0), 16);     // A^8
        else if (j == 4)
            gemm_two<<<dim3(8, 24), 256>>>(s, mkGA(P0, HD_, P0, P1, HD_, HD_, 0), 16);     // A^16
        else
            gemm_one<<<dim3(8, 16), 256>>>(s);
        float* t = cur; cur = nxt; nxt = t;
    }
    // local endpoints F in cur; P = A^16 in P1

    // 5) Hillis-Steele inclusive prefix over 128 chunks (7 rounds):
    //    F'_c = F_{c-s} @ P^s + F_c; apron supplies zeros. Each round (but the
    //    last) fuses the squaring producing P^(2s) for the next round.
    float* Pk = P1; float* Po = P0;
    for (int r = 0; r < 7; r++) {
        const int s = 1 << r;
        GA pre = mkGA(cur + AP - (size_t)16 * s * HD_, HD_, Pk, nxt + AP,
                      HD_, HD_, GF_ADDM, nullptr, nullptr, nullptr, cur + AP);
        if (r < 6) {
            gemm_two<<<dim3(8, 24), 256>>>(pre, mkGA(Pk, HD_, Pk, Po, HD_, HD_, 0), 16);
            float* u = Pk; Pk = Po; Po = u;
        } else {
            gemm_one<<<dim3(8, 16), 256>>>(pre);
        }
        float* t = cur; cur = nxt; nxt = t;
    }
    // inclusive prefix in cur; exclusive prefix = 16 rows back

    // 6) Phase 2: true recurrence per chunk from carry-in; scatter to d_out
    for (int j = 0; j < CH_; j++) {
        const float* Ain = (j == 0) ? (cur + AP - (size_t)16 * HD_) : (cur + AP);
        gemm_one<<<dim3(8, 16), 256>>>(mkGA(Ain, HD_, Amat, nxt + AP, HD_, HD_,
                                            GF_SADD | GF_SSTORE,
                                            nullptr, Bu, outH, nullptr, j));
        float* t = cur; cur = nxt; nxt = t;
    }

    // 7) z = x[:, -1, :] @ W_res + b_res + H_seq_pre[:, -1, :]
    sgemm16<SF_BIAS | SF_ADD><<<16, 256>>>(x + (size_t)(SEQ_ - 1) * LIN_,
                                           (long)SEQ_ * LIN_,
                                           Wres, HD_, Z, HD_, bres,
                                           outH + (size_t)(SEQ_ - 1) * HD_,
                                           (long)SEQ_ * HD_, BATCH_, LIN_);
    // 8) LayerNorm
    ln16<<<BATCH_, 256>>>(Z, lng, lnb, HL);
    // 9) MLP head
    sgemm16<SF_BIAS | SF_RELU><<<FMLP_ / 64, 256>>>(HL, HD_, W1, FMLP_, T, FMLP_,
                                                    b1, nullptr, 0, BATCH_, HD_);
    sgemm16<SF_BIAS><<<HD_ / 64, 256>>>(T, FMLP_, W2, HD_, out0, HD_,
                                        b2, nullptr, 0, BATCH_, FMLP_);
}

// round 14
// speedup vs baseline: 1.2144x; 1.0578x over previous
#include <cuda_runtime.h>
#include <cstdint>

#define BATCH_ 16
#define SEQ_   2048
#define LIN_   256
#define MENC_  512
#define HD_    1024
#define FMLP_  4096
#define CH_    16
#define NCH_   128
#define ROWS_  (NCH_*BATCH_)        // 2048
#define APRON_ 1024
#define FROWS_ (APRON_ + ROWS_)     // 3072

// ---------- scratch (device globals; allocation is forbidden) ----------
__device__ float g_Wx[LIN_*HD_];
__device__ float g_bvec[HD_];
__device__ float g_Bu[(size_t)BATCH_*SEQ_*HD_];
__device__ float g_D1[(size_t)16384*HD_];
__device__ float g_D2[(size_t)8192*HD_];
__device__ float g_P0[HD_*HD_];
__device__ float g_P1[HD_*HD_];
__device__ float g_P2[HD_*HD_];
__device__ float g_FA[(size_t)FROWS_*HD_];
__device__ float g_FB[(size_t)FROWS_*HD_];
__device__ float g_Z [BATCH_*HD_];
__device__ float g_HL[BATCH_*HD_];
__device__ float g_T [BATCH_*FMLP_];

#define GF_BIAS   1
#define GF_SADD   2
#define GF_SSTORE 4
#define GF_ADDM   8

struct GA {
    const float* A; const float* B; float* C;
    const float* bias; const float* scanB; float* scanO; const float* addM;
    int lda, N, K, jstep, flags, addLd;
};

static inline GA mkGA(const float* A, int lda, const float* B, float* C,
                      int N, int K, int flags,
                      const float* bias = nullptr,
                      const float* scanB = nullptr, float* scanO = nullptr,
                      const float* addM = nullptr, int jstep = 0,
                      int addLd = HD_)
{
    GA g; g.A = A; g.B = B; g.C = C; g.bias = bias; g.scanB = scanB;
    g.scanO = scanO; g.addM = addM; g.lda = lda; g.N = N; g.K = K;
    g.jstep = jstep; g.flags = flags; g.addLd = addLd; return g;
}

__device__ __forceinline__ uint32_t s2u(const void* p){
    uint32_t a; asm("{ .reg .u64 t; cvta.to.shared.u64 t,%1; cvt.u32.u64 %0,t; }" : "=r"(a) : "l"(p));
    return a;
}
__device__ __forceinline__ void cpasync16(uint32_t dst, const float* src){
    asm volatile("cp.async.cg.shared.global [%0],[%1],16;" :: "r"(dst), "l"(src));
}
#define CP_COMMIT() asm volatile("cp.async.commit_group;" ::: "memory")
#define CP_WAIT0()  asm volatile("cp.async.wait_group 0;" ::: "memory")

// 128(m) x 128(n) tile, 256 threads (8 warps), 8x8 micro-tile, packed f32x2
// FMA. A: register-staged transpose to k-major smem; B: cp.async bulk copies,
// double-buffered, one __syncthreads per 16-k panel.
__device__ __forceinline__ void gemm_core(const GA& g,
                                          float (&As)[2][16][132],
                                          float (&Bs)[2][16][132],
                                          int bxi, int byi)
{
    const int tid = threadIdx.x;
    const int tm = tid >> 4, tn = tid & 15;
    const int m0 = byi * 128, n0 = bxi * 128;
    const int lar = tid >> 1, lac = (tid & 1) * 8;
    const int N = g.N, K = g.K;

    const float* Aload = g.A + (size_t)(m0 + lar) * g.lda + lac;
    const float* Bload = g.B + n0;
    const uint32_t bsU = s2u(&Bs[0][0][0]);
    const int br = tid >> 5, bc = (tid & 31) * 4;

    unsigned long long acc[4][8];
#pragma unroll
    for (int p = 0; p < 4; p++)
#pragma unroll
        for (int q = 0; q < 8; q++) acc[p][q] = 0ull;

    {
        cpasync16(bsU + ((br * 132 + bc) << 2),       Bload + (size_t)br * N + bc);
        cpasync16(bsU + (((br + 8) * 132 + bc) << 2), Bload + (size_t)(br + 8) * N + bc);
        CP_COMMIT();
        float4 a0 = *(const float4*)(Aload);
        float4 a1 = *(const float4*)(Aload + 4);
        As[0][lac+0][lar]=a0.x; As[0][lac+1][lar]=a0.y; As[0][lac+2][lar]=a0.z; As[0][lac+3][lar]=a0.w;
        As[0][lac+4][lar]=a1.x; As[0][lac+5][lar]=a1.y; As[0][lac+6][lar]=a1.z; As[0][lac+7][lar]=a1.w;
    }

    int buf = 0;
    for (int kt = 0; kt < K; kt += 16) {
        const bool more = (kt + 16) < K;
        CP_WAIT0();
        __syncthreads();
        if (more) {
            const float* Bk = Bload + (size_t)(kt + 16) * N;
            const uint32_t bb = bsU + (uint32_t)((buf ^ 1) * 16 * 132 * 4);
            cpasync16(bb + ((br * 132 + bc) << 2),       Bk + (size_t)br * N + bc);
            cpasync16(bb + (((br + 8) * 132 + bc) << 2), Bk + (size_t)(br + 8) * N + bc);
            CP_COMMIT();
        }
        float4 a0, a1;
        if (more) {
            a0 = *(const float4*)(Aload + kt + 16);
            a1 = *(const float4*)(Aload + kt + 20);
        }
#pragma unroll
        for (int k = 0; k < 16; k++) {
            const ulonglong2 pa0 = *(const ulonglong2*)&As[buf][k][tm * 8];
            const ulonglong2 pa1 = *(const ulonglong2*)&As[buf][k][tm * 8 + 4];
            const float4 x = *(const float4*)&Bs[buf][k][tn * 8];
            const float4 y = *(const float4*)&Bs[buf][k][tn * 8 + 4];
            unsigned long long pb[8];
            asm("mov.b64 %0,{%1,%1};" : "=l"(pb[0]) : "f"(x.x));
            asm("mov.b64 %0,{%1,%1};" : "=l"(pb[1]) : "f"(x.y));
            asm("mov.b64 %0,{%1,%1};" : "=l"(pb[2]) : "f"(x.z));
            asm("mov.b64 %0,{%1,%1};" : "=l"(pb[3]) : "f"(x.w));
            asm("mov.b64 %0,{%1,%1};" : "=l"(pb[4]) : "f"(y.x));
            asm("mov.b64 %0,{%1,%1};" : "=l"(pb[5]) : "f"(y.y));
            asm("mov.b64 %0,{%1,%1};" : "=l"(pb[6]) : "f"(y.z));
            asm("mov.b64 %0,{%1,%1};" : "=l"(pb[7]) : "f"(y.w));
#pragma unroll
            for (int q = 0; q < 8; q++) {
                asm("fma.rn.f32x2 %0,%1,%2,%0;" : "+l"(acc[0][q]) : "l"(pa0.x), "l"(pb[q]));
                asm("fma.rn.f32x2 %0,%1,%2,%0;" : "+l"(acc[1][q]) : "l"(pa0.y), "l"(pb[q]));
                asm("fma.rn.f32x2 %0,%1,%2,%0;" : "+l"(acc[2][q]) : "l"(pa1.x), "l"(pb[q]));
                asm("fma.rn.f32x2 %0,%1,%2,%0;" : "+l"(acc[3][q]) : "l"(pa1.y), "l"(pb[q]));
            }
        }
        if (more) {
            const int nb = buf ^ 1;
            As[nb][lac+0][lar]=a0.x; As[nb][lac+1][lar]=a0.y; As[nb][lac+2][lar]=a0.z; As[nb][lac+3][lar]=a0.w;
            As[nb][lac+4][lar]=a1.x; As[nb][lac+5][lar]=a1.y; As[nb][lac+6][lar]=a1.z; As[nb][lac+7][lar]=a1.w;
        }
        buf ^= 1;
    }

    float cv[8][8];
#pragma unroll
    for (int p = 0; p < 4; p++)
#pragma unroll
        for (int q = 0; q < 8; q++)
            asm("mov.b64 {%0,%1},%2;"
                : "=f"(cv[2*p][q]), "=f"(cv[2*p+1][q]) : "l"(acc[p][q]));

    const int F = g.flags;
    const int gc = n0 + tn * 8;
    float4 bv0 = make_float4(0.f,0.f,0.f,0.f), bv1 = bv0;
    if (F & GF_BIAS) {
        bv0 = *(const float4*)(g.bias + gc);
        bv1 = *(const float4*)(g.bias + gc + 4);
    }
#pragma unroll
    for (int mr = 0; mr < 8; mr++) {
        const int gm = m0 + tm * 8 + mr;
        float4 v0 = make_float4(cv[mr][0], cv[mr][1], cv[mr][2], cv[mr][3]);
        float4 v1 = make_float4(cv[mr][4], cv[mr][5], cv[mr][6], cv[mr][7]);
        if (F & GF_BIAS) {
            v0.x += bv0.x; v0.y += bv0.y; v0.z += bv0.z; v0.w += bv0.w;
            v1.x += bv1.x; v1.y += bv1.y; v1.z += bv1.z; v1.w += bv1.w;
        }
        if (F & GF_ADDM) {
            const float* ap = g.addM + (size_t)gm * g.addLd + gc;
            float4 u0 = *(const float4*)(ap);
            float4 u1 = *(const float4*)(ap + 4);
            v0.x += u0.x; v0.y += u0.y; v0.z += u0.z; v0.w += u0.w;
            v1.x += u1.x; v1.y += u1.y; v1.z += u1.z; v1.w += u1.w;
        }
        size_t soff = 0;
        if (F & (GF_SADD | GF_SSTORE))
            soff = ((size_t)(gm & 15) * SEQ_ + (size_t)(gm >> 4) * CH_ + g.jstep) * HD_ + gc;
        if (F & GF_SADD) {
            float4 s0 = *(const float4*)(g.scanB + soff);
            float4 s1 = *(const float4*)(g.scanB + soff + 4);
            v0.x += s0.x; v0.y += s0.y; v0.z += s0.z; v0.w += s0.w;
            v1.x += s1.x; v1.y += s1.y; v1.z += s1.z; v1.w += s1.w;
        }
        *(float4*)(g.C + (size_t)gm * N + gc)     = v0;
        *(float4*)(g.C + (size_t)gm * N + gc + 4) = v1;
        if (F & GF_SSTORE) {
            *(float4*)(g.scanO + soff)     = v0;
            *(float4*)(g.scanO + soff + 4) = v1;
        }
    }
}

__global__ void __launch_bounds__(256, 2) gemm_one(GA g)
{
    __shared__ float As[2][16][132];
    __shared__ float Bs[2][16][132];
    gemm_core(g, As, Bs, blockIdx.x, blockIdx.y);
}

// Two independent GEMM segments in one launch (split on blockIdx.y).
__global__ void __launch_bounds__(256, 2) gemm_two(GA g1, GA g2, int bySplit)
{
    __shared__ float As[2][16][132];
    __shared__ float Bs[2][16][132];
    if ((int)blockIdx.y < bySplit)
        gemm_core(g1, As, Bs, blockIdx.x, blockIdx.y);
    else
        gemm_core(g2, As, Bs, blockIdx.x, blockIdx.y - bySplit);
}

#define SF_BIAS 1
#define SF_RELU 2
#define SF_ADD  4

template<int F>
__global__ void __launch_bounds__(256)
sgemm16(const float* __restrict__ Ap, long lda,
        const float* __restrict__ Bp, int ldb,
        float* __restrict__ Cp, int ldc,
        const float* __restrict__ bias,
        const float* __restrict__ addend, long ldadd,
        int M, int K)
{
    __shared__ float As[16][33];
    const int tid = threadIdx.x;
    const int c = tid & 63, g = tid >> 6;
    const int col = blockIdx.x * 64 + c;
    float acc[4] = {0.f, 0.f, 0.f, 0.f};
    for (int k0 = 0; k0 < K; k0 += 32) {
        __syncthreads();
        for (int e = tid; e < 512; e += 256) {
            const int r = e >> 5, kk = e & 31;
            As[r][kk] = (r < M) ? Ap[(size_t)r * lda + k0 + kk] : 0.f;
        }
        __syncthreads();
#pragma unroll 8
        for (int kk = 0; kk < 32; kk++) {
            const float bv = Bp[(size_t)(k0 + kk) * ldb + col];
#pragma unroll
            for (int i = 0; i < 4; i++) acc[i] += As[g * 4 + i][kk] * bv;
        }
    }
#pragma unroll
    for (int i = 0; i < 4; i++) {
        const int r = g * 4 + i;
        if (r < M) {
            float v = acc[i];
            if (F & SF_BIAS) v += bias[col];
            if (F & SF_ADD)  v += addend[(size_t)r * ldadd + col];
            if (F & SF_RELU) v = fmaxf(v, 0.f);
            Cp[(size_t)r * ldc + col] = v;
        }
    }
}

__global__ void __launch_bounds__(256)
ln16(const float* __restrict__ z, const float* __restrict__ gam,
     const float* __restrict__ bet, float* __restrict__ o)
{
    __shared__ float s1[8], s2[8];
    const int b = blockIdx.x, tid = threadIdx.x;
    float4 v = ((const float4*)(z + (size_t)b * HD_))[tid];
    float s = v.x + v.y + v.z + v.w;
    float q = v.x*v.x + v.y*v.y + v.z*v.z + v.w*v.w;
    for (int d = 16; d > 0; d >>= 1) {
        s += __shfl_xor_sync(0xffffffffu, s, d);
        q += __shfl_xor_sync(0xffffffffu, q, d);
    }
    if ((tid & 31) == 0) { s1[tid >> 5] = s; s2[tid >> 5] = q; }
    __syncthreads();
    if (tid < 8) {
        s = s1[tid]; q = s2[tid];
        for (int d = 4; d > 0; d >>= 1) {
            s += __shfl_xor_sync(0xffu, s, d);
            q += __shfl_xor_sync(0xffu, q, d);
        }
        if (tid == 0) { s1[0] = s; s2[0] = q; }
    }
    __syncthreads();
    const float mu = s1[0] * (1.f / HD_);
    const float var = s2[0] * (1.f / HD_) - mu * mu;
    const float rs = rsqrtf(var + 1e-5f);
    float4 gg = ((const float4*)gam)[tid];
    float4 bb = ((const float4*)bet)[tid];
    float4 r;
    r.x = (v.x - mu) * rs * gg.x + bb.x;
    r.y = (v.y - mu) * rs * gg.y + bb.y;
    r.z = (v.z - mu) * rs * gg.z + bb.z;
    r.w = (v.w - mu) * rs * gg.w + bb.w;
    ((float4*)(o + (size_t)b * HD_))[tid] = r;
}

// remap batch-major endpoints (row b*128+c) -> scan layout (row c*16+b)
__global__ void remapE(const float* __restrict__ s, float* __restrict__ d)
{
    const int r = blockIdx.x;
    const int b = r >> 7, c = r & 127;
    ((float4*)(d + (size_t)(c * 16 + b) * HD_))[threadIdx.x] =
        ((const float4*)(s + (size_t)r * HD_))[threadIdx.x];
}

__global__ void zero4(float* p)
{
    ((float4*)p)[(size_t)blockIdx.x * 256 + threadIdx.x] = make_float4(0.f, 0.f, 0.f, 0.f);
}

extern "C" void kernel_launch(void* const* d_in, const int* in_sizes, int n_in,
                              void* d_out, int out_size)
{
    (void)in_sizes; (void)n_in; (void)out_size;
    const float* x    = (const float*)d_in[0];
    const float* Wenc = (const float*)d_in[1];
    const float* benc = (const float*)d_in[2];
    const float* WB   = (const float*)d_in[3];
    const float* Amat = (const float*)d_in[4];
    const float* Wres = (const float*)d_in[5];
    const float* bres = (const float*)d_in[6];
    const float* lng  = (const float*)d_in[7];
    const float* lnb  = (const float*)d_in[8];
    const float* W1   = (const float*)d_in[9];
    const float* b1   = (const float*)d_in[10];
    const float* W2   = (const float*)d_in[11];
    const float* b2   = (const float*)d_in[12];
    float* out0 = (float*)d_out;                 // (16,1024) MLP head
    float* outH = out0 + BATCH_ * HD_;           // (16,2048,1024) H_seq_pre

    float *Wx, *bvec, *Bu, *D1, *D2, *P0, *P1, *P2, *FA, *FB, *Z, *HL, *T;
    cudaGetSymbolAddress((void**)&Wx,   g_Wx);
    cudaGetSymbolAddress((void**)&bvec, g_bvec);
    cudaGetSymbolAddress((void**)&Bu,   g_Bu);
    cudaGetSymbolAddress((void**)&D1,   g_D1);
    cudaGetSymbolAddress((void**)&D2,   g_D2);
    cudaGetSymbolAddress((void**)&P0,   g_P0);
    cudaGetSymbolAddress((void**)&P1,   g_P1);
    cudaGetSymbolAddress((void**)&P2,   g_P2);
    cudaGetSymbolAddress((void**)&FA,   g_FA);
    cudaGetSymbolAddress((void**)&FB,   g_FB);
    cudaGetSymbolAddress((void**)&Z,    g_Z);
    cudaGetSymbolAddress((void**)&HL,   g_HL);
    cudaGetSymbolAddress((void**)&T,    g_T);

    const size_t AP = (size_t)APRON_ * HD_;

    // 0) zero aprons first (also shifts ncu capture onto real GEMMs)
    zero4<<<1024, 256>>>(FA);
    zero4<<<1024, 256>>>(FB);

    // 1) Wx = W_enc @ W_B ; bvec = b_enc @ W_B
    gemm_one<<<dim3(8, 4), 256>>>(mkGA(Wenc, MENC_, WB, Wx, HD_, MENC_, 0));
    sgemm16<0><<<16, 256>>>(benc, MENC_, WB, HD_, bvec, HD_,
                            nullptr, nullptr, 0, 1, MENC_);

    // 2) Bu = x2d @ Wx + bvec   (32768 x 1024, K=256)
    gemm_one<<<dim3(8, 256), 256>>>(mkGA(x, LIN_, Wx, Bu, HD_, LIN_, GF_BIAS, bvec));

    // 3) Phase 1 by pairwise doubling (4 serial levels), squarings fused:
    //    C1[b,p] = Bu[b,2p]@A   + Bu[b,2p+1]   (16384 rows)  | A^2  = A@A
    //    C2[b,q] = C1[b,2q]@A^2 + C1[b,2q+1]   ( 8192 rows)  | A^4  = A^2@A^2
    //    C3[b,v] = C2[b,2v]@A^4 + C2[b,2v+1]   ( 4096 rows)  | A^8  = A^4@A^4
    //    C4[b,c] = C3[b,2c]@A^8 + C3[b,2c+1]   ( 2048 rows)  | A^16 = A^8@A^8
    gemm_two<<<dim3(8, 136), 256>>>(
        mkGA(Bu, 2*HD_, Amat, D1, HD_, HD_, GF_ADDM, nullptr, nullptr, nullptr,
             Bu + HD_, 0, 2*HD_),
        mkGA(Amat, HD_, Amat, P0, HD_, HD_, 0), 128);
    gemm_two<<<dim3(8, 72), 256>>>(
        mkGA(D1, 2*HD_, P0, D2, HD_, HD_, GF_ADDM, nullptr, nullptr, nullptr,
             D1 + HD_, 0, 2*HD_),
        mkGA(P0, HD_, P0, P1, HD_, HD_, 0), 64);
    gemm_two<<<dim3(8, 40), 256>>>(
        mkGA(D2, 2*HD_, P1, D1, HD_, HD_, GF_ADDM, nullptr, nullptr, nullptr,
             D2 + HD_, 0, 2*HD_),
        mkGA(P1, HD_, P1, P2, HD_, HD_, 0), 32);
    gemm_two<<<dim3(8, 24), 256>>>(
        mkGA(D1, 2*HD_, P2, D2, HD_, HD_, GF_ADDM, nullptr, nullptr, nullptr,
             D1 + HD_, 0, 2*HD_),
        mkGA(P2, HD_, P2, P0, HD_, HD_, 0), 16);
    // endpoints (batch-major) -> scan layout at FA+AP; P0 = A^16
    remapE<<<ROWS_, 256>>>(D2, FA + AP);

    // 4) Hillis-Steele inclusive prefix over 128 chunks (7 rounds),
    //    squaring P between rounds (fused segment).
    float* cur = FA; float* nxt = FB;
    float* Pk = P0; float* Po = P1;
    for (int r = 0; r < 7; r++) {
        const int s = 1 << r;
        GA pre = mkGA(cur + AP - (size_t)16 * s * HD_, HD_, Pk, nxt + AP,
                      HD_, HD_, GF_ADDM, nullptr, nullptr, nullptr, cur + AP);
        if (r < 6) {
            gemm_two<<<dim3(8, 24), 256>>>(pre, mkGA(Pk, HD_, Pk, Po, HD_, HD_, 0), 16);
            float* u = Pk; Pk = Po; Po = u;
        } else {
            gemm_one<<<dim3(8, 16), 256>>>(pre);
        }
        float* t = cur; cur = nxt; nxt = t;
    }
    // inclusive prefix in cur; exclusive prefix = 16 rows back

    // 5) Phase 2: true recurrence per chunk from carry-in; scatter to d_out
    for (int j = 0; j < CH_; j++) {
        const float* Ain = (j == 0) ? (cur + AP - (size_t)16 * HD_) : (cur + AP);
        gemm_one<<<dim3(8, 16), 256>>>(mkGA(Ain, HD_, Amat, nxt + AP, HD_, HD_,
                                            GF_SADD | GF_SSTORE,
                                            nullptr, Bu, outH, nullptr, j));
        float* t = cur; cur = nxt; nxt = t;
    }

    // 6) z = x[:, -1, :] @ W_res + b_res + H_seq_pre[:, -1, :]
    sgemm16<SF_BIAS | SF_ADD><<<16, 256>>>(x + (size_t)(SEQ_ - 1) * LIN_,
                                           (long)SEQ_ * LIN_,
                                           Wres, HD_, Z, HD_, bres,
                                           outH + (size_t)(SEQ_ - 1) * HD_,
                                           (long)SEQ_ * HD_, BATCH_, LIN_);
    // 7) LayerNorm
    ln16<<<BATCH_, 256>>>(Z, lng, lnb, HL);
    // 8) MLP head
    sgemm16<SF_BIAS | SF_RELU><<<FMLP_ / 64, 256>>>(HL, HD_, W1, FMLP_, T, FMLP_,
                                                    b1, nullptr, 0, BATCH_, HD_);
    sgemm16<SF_BIAS><<<HD_ / 64, 256>>>(T, FMLP_, W2, HD_, out0, HD_,
                                        b2, nullptr, 0, BATCH_, FMLP_);
}

// round 15
// speedup vs baseline: 1.2331x; 1.0153x over previous
#include <cuda_runtime.h>
#include <cstdint>

#define BATCH_ 16
#define SEQ_   2048
#define LIN_   256
#define MENC_  512
#define HD_    1024
#define FMLP_  4096
#define CH_    16
#define NCH_   128
#define ROWS_  (NCH_*BATCH_)        // 2048
#define APRON_ 1024
#define FROWS_ (APRON_ + ROWS_)     // 3072

// ---------- scratch (device globals; allocation is forbidden) ----------
__device__ float g_WE[(size_t)384*MENC_];     // [Wenc; benc; zeros] staging
__device__ float g_WxB[(size_t)384*HD_];      // rows 0-255 Wx, row 256 bvec
__device__ float g_Bu[(size_t)BATCH_*SEQ_*HD_];
__device__ float g_D1[(size_t)16384*HD_];
__device__ float g_D2[(size_t)8192*HD_];
__device__ float g_P0[HD_*HD_];
__device__ float g_P1[HD_*HD_];
__device__ float g_P2[HD_*HD_];
__device__ float g_FA[(size_t)FROWS_*HD_];
__device__ float g_FB[(size_t)FROWS_*HD_];
__device__ float g_Z [BATCH_*HD_];
__device__ float g_HL[BATCH_*HD_];
__device__ float g_T [BATCH_*FMLP_];
__device__ unsigned g_ctr[32];                // persistent-kernel barrier counters

#define GF_BIAS   1
#define GF_SADD   2
#define GF_SSTORE 4
#define GF_ADDM   8

struct GA {
    const float* A; const float* B; float* C;
    const float* bias; const float* scanB; float* scanO; const float* addM;
    int lda, N, K, jstep, flags, addLd;
};

__host__ __device__ static inline GA mkGA(const float* A, int lda, const float* B, float* C,
                      int N, int K, int flags,
                      const float* bias = nullptr,
                      const float* scanB = nullptr, float* scanO = nullptr,
                      const float* addM = nullptr, int jstep = 0,
                      int addLd = HD_)
{
    GA g; g.A = A; g.B = B; g.C = C; g.bias = bias; g.scanB = scanB;
    g.scanO = scanO; g.addM = addM; g.lda = lda; g.N = N; g.K = K;
    g.jstep = jstep; g.flags = flags; g.addLd = addLd; return g;
}

__device__ __forceinline__ uint32_t s2u(const void* p){
    uint32_t a; asm("{ .reg .u64 t; cvta.to.shared.u64 t,%1; cvt.u32.u64 %0,t; }" : "=r"(a) : "l"(p));
    return a;
}
__device__ __forceinline__ void cpasync16(uint32_t dst, const float* src){
    asm volatile("cp.async.cg.shared.global [%0],[%1],16;" :: "r"(dst), "l"(src));
}
#define CP_COMMIT() asm volatile("cp.async.commit_group;" ::: "memory")
#define CP_WAIT0()  asm volatile("cp.async.wait_group 0;" ::: "memory")
// L2-only load (L1 may be stale across grid-barrier steps in the persistent kernel)
__device__ __forceinline__ float4 ldgcg4(const float* p){
    float4 v;
    asm volatile("ld.global.cg.v4.f32 {%0,%1,%2,%3},[%4];"
                 : "=f"(v.x),"=f"(v.y),"=f"(v.z),"=f"(v.w) : "l"(p));
    return v;
}

// 128x128 tile, 256 threads, 8x8 micro-tile, packed f32x2 FMA.
// A: register-staged transpose (ld.global.cg); B: cp.async double-buffered,
// one __syncthreads per 16-k panel.
__device__ __forceinline__ void gemm_core(const GA& g,
                                          float (&As)[2][16][132],
                                          float (&Bs)[2][16][132],
                                          int bxi, int byi)
{
    const int tid = threadIdx.x;
    const int tm = tid >> 4, tn = tid & 15;
    const int m0 = byi * 128, n0 = bxi * 128;
    const int lar = tid >> 1, lac = (tid & 1) * 8;
    const int N = g.N, K = g.K;

    const float* Aload = g.A + (size_t)(m0 + lar) * g.lda + lac;
    const float* Bload = g.B + n0;
    const uint32_t bsU = s2u(&Bs[0][0][0]);
    const int br = tid >> 5, bc = (tid & 31) * 4;

    unsigned long long acc[4][8];
#pragma unroll
    for (int p = 0; p < 4; p++)
#pragma unroll
        for (int q = 0; q < 8; q++) acc[p][q] = 0ull;

    {
        cpasync16(bsU + ((br * 132 + bc) << 2),       Bload + (size_t)br * N + bc);
        cpasync16(bsU + (((br + 8) * 132 + bc) << 2), Bload + (size_t)(br + 8) * N + bc);
        CP_COMMIT();
        float4 a0 = ldgcg4(Aload);
        float4 a1 = ldgcg4(Aload + 4);
        As[0][lac+0][lar]=a0.x; As[0][lac+1][lar]=a0.y; As[0][lac+2][lar]=a0.z; As[0][lac+3][lar]=a0.w;
        As[0][lac+4][lar]=a1.x; As[0][lac+5][lar]=a1.y; As[0][lac+6][lar]=a1.z; As[0][lac+7][lar]=a1.w;
    }

    int buf = 0;
    for (int kt = 0; kt < K; kt += 16) {
        const bool more = (kt + 16) < K;
        CP_WAIT0();
        __syncthreads();
        if (more) {
            const float* Bk = Bload + (size_t)(kt + 16) * N;
            const uint32_t bb = bsU + (uint32_t)((buf ^ 1) * 16 * 132 * 4);
            cpasync16(bb + ((br * 132 + bc) << 2),       Bk + (size_t)br * N + bc);
            cpasync16(bb + (((br + 8) * 132 + bc) << 2), Bk + (size_t)(br + 8) * N + bc);
            CP_COMMIT();
        }
        float4 a0, a1;
        if (more) {
            a0 = ldgcg4(Aload + kt + 16);
            a1 = ldgcg4(Aload + kt + 20);
        }
#pragma unroll
        for (int k = 0; k < 16; k++) {
            const ulonglong2 pa0 = *(const ulonglong2*)&As[buf][k][tm * 8];
            const ulonglong2 pa1 = *(const ulonglong2*)&As[buf][k][tm * 8 + 4];
            const float4 x = *(const float4*)&Bs[buf][k][tn * 8];
            const float4 y = *(const float4*)&Bs[buf][k][tn * 8 + 4];
            unsigned long long pb[8];
            asm("mov.b64 %0,{%1,%1};" : "=l"(pb[0]) : "f"(x.x));
            asm("mov.b64 %0,{%1,%1};" : "=l"(pb[1]) : "f"(x.y));
            asm("mov.b64 %0,{%1,%1};" : "=l"(pb[2]) : "f"(x.z));
            asm("mov.b64 %0,{%1,%1};" : "=l"(pb[3]) : "f"(x.w));
            asm("mov.b64 %0,{%1,%1};" : "=l"(pb[4]) : "f"(y.x));
            asm("mov.b64 %0,{%1,%1};" : "=l"(pb[5]) : "f"(y.y));
            asm("mov.b64 %0,{%1,%1};" : "=l"(pb[6]) : "f"(y.z));
            asm("mov.b64 %0,{%1,%1};" : "=l"(pb[7]) : "f"(y.w));
#pragma unroll
            for (int q = 0; q < 8; q++) {
                asm("fma.rn.f32x2 %0,%1,%2,%0;" : "+l"(acc[0][q]) : "l"(pa0.x), "l"(pb[q]));
                asm("fma.rn.f32x2 %0,%1,%2,%0;" : "+l"(acc[1][q]) : "l"(pa0.y), "l"(pb[q]));
                asm("fma.rn.f32x2 %0,%1,%2,%0;" : "+l"(acc[2][q]) : "l"(pa1.x), "l"(pb[q]));
                asm("fma.rn.f32x2 %0,%1,%2,%0;" : "+l"(acc[3][q]) : "l"(pa1.y), "l"(pb[q]));
            }
        }
        if (more) {
            const int nb = buf ^ 1;
            As[nb][lac+0][lar]=a0.x; As[nb][lac+1][lar]=a0.y; As[nb][lac+2][lar]=a0.z; As[nb][lac+3][lar]=a0.w;
            As[nb][lac+4][lar]=a1.x; As[nb][lac+5][lar]=a1.y; As[nb][lac+6][lar]=a1.z; As[nb][lac+7][lar]=a1.w;
        }
        buf ^= 1;
    }

    float cv[8][8];
#pragma unroll
    for (int p = 0; p < 4; p++)
#pragma unroll
        for (int q = 0; q < 8; q++)
            asm("mov.b64 {%0,%1},%2;"
                : "=f"(cv[2*p][q]), "=f"(cv[2*p+1][q]) : "l"(acc[p][q]));

    const int F = g.flags;
    const int gc = n0 + tn * 8;
    float4 bv0 = make_float4(0.f,0.f,0.f,0.f), bv1 = bv0;
    if (F & GF_BIAS) {
        bv0 = *(const float4*)(g.bias + gc);
        bv1 = *(const float4*)(g.bias + gc + 4);
    }
#pragma unroll
    for (int mr = 0; mr < 8; mr++) {
        const int gm = m0 + tm * 8 + mr;
        float4 v0 = make_float4(cv[mr][0], cv[mr][1], cv[mr][2], cv[mr][3]);
        float4 v1 = make_float4(cv[mr][4], cv[mr][5], cv[mr][6], cv[mr][7]);
        if (F & GF_BIAS) {
            v0.x += bv0.x; v0.y += bv0.y; v0.z += bv0.z; v0.w += bv0.w;
            v1.x += bv1.x; v1.y += bv1.y; v1.z += bv1.z; v1.w += bv1.w;
        }
        if (F & GF_ADDM) {
            const float* ap = g.addM + (size_t)gm * g.addLd + gc;
            float4 u0 = *(const float4*)(ap);
            float4 u1 = *(const float4*)(ap + 4);
            v0.x += u0.x; v0.y += u0.y; v0.z += u0.z; v0.w += u0.w;
            v1.x += u1.x; v1.y += u1.y; v1.z += u1.z; v1.w += u1.w;
        }
        size_t soff = 0;
        if (F & (GF_SADD | GF_SSTORE))
            soff = ((size_t)(gm & 15) * SEQ_ + (size_t)(gm >> 4) * CH_ + g.jstep) * HD_ + gc;
        if (F & GF_SADD) {
            float4 s0 = *(const float4*)(g.scanB + soff);
            float4 s1 = *(const float4*)(g.scanB + soff + 4);
            v0.x += s0.x; v0.y += s0.y; v0.z += s0.z; v0.w += s0.w;
            v1.x += s1.x; v1.y += s1.y; v1.z += s1.z; v1.w += s1.w;
        }
        *(float4*)(g.C + (size_t)gm * N + gc)     = v0;
        *(float4*)(g.C + (size_t)gm * N + gc + 4) = v1;
        if (F & GF_SSTORE) {
            *(float4*)(g.scanO + soff)     = v0;
            *(float4*)(g.scanO + soff + 4) = v1;
        }
    }
}

__global__ void __launch_bounds__(256, 2) gemm_one(GA g)
{
    __shared__ float As[2][16][132];
    __shared__ float Bs[2][16][132];
    gemm_core(g, As, Bs, blockIdx.x, blockIdx.y);
}

__global__ void __launch_bounds__(256, 2) gemm_two(GA g1, GA g2, int bySplit)
{
    __shared__ float As[2][16][132];
    __shared__ float Bs[2][16][132];
    if ((int)blockIdx.y < bySplit)
        gemm_core(g1, As, Bs, blockIdx.x, blockIdx.y);
    else
        gemm_core(g2, As, Bs, blockIdx.x, blockIdx.y - bySplit);
}

// Persistent phase-2: 16 scan steps in one launch, grid barrier between steps.
// MUST be launched with exactly dim3(8,16) blocks (all co-resident).
__global__ void __launch_bounds__(256, 2)
scan2(float* bufA, float* bufB, const float* Amat,
      const float* Bu, float* outH)
{
    __shared__ float As[2][16][132];
    __shared__ float Bs[2][16][132];
    const size_t AP = (size_t)APRON_ * HD_;
    float* cur = bufA;
    float* nxt = bufB;
    for (int j = 0; j < CH_; j++) {
        const float* Ain = (j == 0) ? (cur + AP - (size_t)16 * HD_) : (cur + AP);
        GA g = mkGA(Ain, HD_, Amat, nxt + AP, HD_, HD_, GF_SADD | GF_SSTORE,
                    nullptr, Bu, outH, nullptr, j);
        gemm_core(g, As, Bs, blockIdx.x, blockIdx.y);
        // grid barrier (release: fence + atomic arrive; acquire: volatile spin)
        __syncthreads();
        __threadfence();
        if (threadIdx.x == 0) {
            atomicAdd(&g_ctr[j], 1u);
            while (*(volatile unsigned*)&g_ctr[j] < 128u) {}
        }
        __syncthreads();
        float* t = cur; cur = nxt; nxt = t;
    }
}

__global__ void zeroCtr()
{
    if (threadIdx.x < 32) g_ctr[threadIdx.x] = 0u;
}

#define SF_BIAS 1
#define SF_RELU 2
#define SF_ADD  4

// Small-M (<=16) GEMM with 4-way k-split: 256 threads = 64 cols x 4 k-groups,
// deterministic smem reduction. K must be a multiple of 128.
template<int F>
__global__ void __launch_bounds__(256)
sgemmKS(const float* __restrict__ Ap, long lda,
        const float* __restrict__ Bp, int ldb,
        float* __restrict__ Cp, int ldc,
        const float* __restrict__ bias,
        const float* __restrict__ addend, long ldadd,
        int M, int K)
{
    __shared__ float As[4][16][33];
    __shared__ float Rs[4][16][64];
    const int tid = threadIdx.x;
    const int c = tid & 63, g = tid >> 6;
    const int col = blockIdx.x * 64 + c;
    const int kQ = K >> 2;
    float acc[16];
#pragma unroll
    for (int r = 0; r < 16; r++) acc[r] = 0.f;
    for (int k0 = 0; k0 < kQ; k0 += 32) {
        __syncthreads();
        for (int e = tid; e < 2048; e += 256) {
            const int gg = e >> 9, rem = e & 511, r = rem >> 5, kk = rem & 31;
            As[gg][r][kk] = (r < M) ? Ap[(size_t)r * lda + gg * kQ + k0 + kk] : 0.f;
        }
        __syncthreads();
#pragma unroll 8
        for (int kk = 0; kk < 32; kk++) {
            const float bv = Bp[(size_t)(g * kQ + k0 + kk) * ldb + col];
#pragma unroll
            for (int r = 0; r < 16; r++) acc[r] += As[g][r][kk] * bv;
        }
    }
    __syncthreads();
#pragma unroll
    for (int r = 0; r < 16; r++) Rs[g][r][c] = acc[r];
    __syncthreads();
    if (g == 0) {
#pragma unroll
        for (int r = 0; r < 16; r++) {
            if (r < M) {
                float v = Rs[0][r][c] + Rs[1][r][c] + Rs[2][r][c] + Rs[3][r][c];
                if (F & SF_BIAS) v += bias[col];
                if (F & SF_ADD)  v += addend[(size_t)r * ldadd + col];
                if (F & SF_RELU) v = fmaxf(v, 0.f);
                Cp[(size_t)r * ldc + col] = v;
            }
        }
    }
}

__global__ void __launch_bounds__(256)
ln16(const float* __restrict__ z, const float* __restrict__ gam,
     const float* __restrict__ bet, float* __restrict__ o)
{
    __shared__ float s1[8], s2[8];
    const int b = blockIdx.x, tid = threadIdx.x;
    float4 v = ((const float4*)(z + (size_t)b * HD_))[tid];
    float s = v.x + v.y + v.z + v.w;
    float q = v.x*v.x + v.y*v.y + v.z*v.z + v.w*v.w;
    for (int d = 16; d > 0; d >>= 1) {
        s += __shfl_xor_sync(0xffffffffu, s, d);
        q += __shfl_xor_sync(0xffffffffu, q, d);
    }
    if ((tid & 31) == 0) { s1[tid >> 5] = s; s2[tid >> 5] = q; }
    __syncthreads();
    if (tid < 8) {
        s = s1[tid]; q = s2[tid];
        for (int d = 4; d > 0; d >>= 1) {
            s += __shfl_xor_sync(0xffu, s, d);
            q += __shfl_xor_sync(0xffu, q, d);
        }
        if (tid == 0) { s1[0] = s; s2[0] = q; }
    }
    __syncthreads();
    const float mu = s1[0] * (1.f / HD_);
    const float var = s2[0] * (1.f / HD_) - mu * mu;
    const float rs = rsqrtf(var + 1e-5f);
    float4 gg = ((const float4*)gam)[tid];
    float4 bb = ((const float4*)bet)[tid];
    float4 r;
    r.x = (v.x - mu) * rs * gg.x + bb.x;
    r.y = (v.y - mu) * rs * gg.y + bb.y;
    r.z = (v.z - mu) * rs * gg.z + bb.z;
    r.w = (v.w - mu) * rs * gg.w + bb.w;
    ((float4*)(o + (size_t)b * HD_))[tid] = r;
}

// remap batch-major endpoints (row b*128+c) -> scan layout (row c*16+b)
__global__ void remapE(const float* __restrict__ s, float* __restrict__ d)
{
    const int r = blockIdx.x;
    const int b = r >> 7, c = r & 127;
    ((float4*)(d + (size_t)(c * 16 + b) * HD_))[threadIdx.x] =
        ((const float4*)(s + (size_t)r * HD_))[threadIdx.x];
}

__global__ void zero4(float* p)
{
    ((float4*)p)[(size_t)blockIdx.x * 256 + threadIdx.x] = make_float4(0.f, 0.f, 0.f, 0.f);
}

// stage [Wenc(256 rows); benc(1); zeros(127)] into a 384x512 buffer
__global__ void stageWE(const float* __restrict__ Wenc,
                        const float* __restrict__ benc, float* __restrict__ S)
{
    const int r = blockIdx.x, i = threadIdx.x;
    float2 v = make_float2(0.f, 0.f);
    if (r < 256)       v = ((const float2*)(Wenc + (size_t)r * MENC_))[i];
    else if (r == 256) v = ((const float2*)benc)[i];
    ((float2*)(S + (size_t)r * MENC_))[i] = v;
}

extern "C" void kernel_launch(void* const* d_in, const int* in_sizes, int n_in,
                              void* d_out, int out_size)
{
    (void)in_sizes; (void)n_in; (void)out_size;
    const float* x    = (const float*)d_in[0];
    const float* Wenc = (const float*)d_in[1];
    const float* benc = (const float*)d_in[2];
    const float* WB   = (const float*)d_in[3];
    const float* Amat = (const float*)d_in[4];
    const float* Wres = (const float*)d_in[5];
    const float* bres = (const float*)d_in[6];
    const float* lng  = (const float*)d_in[7];
    const float* lnb  = (const float*)d_in[8];
    const float* W1   = (const float*)d_in[9];
    const float* b1   = (const float*)d_in[10];
    const float* W2   = (const float*)d_in[11];
    const float* b2   = (const float*)d_in[12];
    float* out0 = (float*)d_out;                 // (16,1024) MLP head
    float* outH = out0 + BATCH_ * HD_;           // (16,2048,1024) H_seq_pre

    float *WE, *WxB, *Bu, *D1, *D2, *P0, *P1, *P2, *FA, *FB, *Z, *HL, *T;
    cudaGetSymbolAddress((void**)&WE,   g_WE);
    cudaGetSymbolAddress((void**)&WxB,  g_WxB);
    cudaGetSymbolAddress((void**)&Bu,   g_Bu);
    cudaGetSymbolAddress((void**)&D1,   g_D1);
    cudaGetSymbolAddress((void**)&D2,   g_D2);
    cudaGetSymbolAddress((void**)&P0,   g_P0);
    cudaGetSymbolAddress((void**)&P1,   g_P1);
    cudaGetSymbolAddress((void**)&P2,   g_P2);
    cudaGetSymbolAddress((void**)&FA,   g_FA);
    cudaGetSymbolAddress((void**)&FB,   g_FB);
    cudaGetSymbolAddress((void**)&Z,    g_Z);
    cudaGetSymbolAddress((void**)&HL,   g_HL);
    cudaGetSymbolAddress((void**)&T,    g_T);

    const size_t AP = (size_t)APRON_ * HD_;

    // 0) zero barrier counters + aprons
    zeroCtr<<<1, 32>>>();
    zero4<<<1024, 256>>>(FA);
    zero4<<<1024, 256>>>(FB);

    // 1) [Wx; bvec] = [Wenc; benc] @ WB  (one 384x1024 GEMM)
    stageWE<<<384, 256>>>(Wenc, benc, WE);
    gemm_one<<<dim3(8, 3), 256>>>(mkGA(WE, MENC_, WB, WxB, HD_, MENC_, 0));

    // 2) Bu = x2d @ Wx + bvec   (32768 x 1024, K=256)
    gemm_one<<<dim3(8, 256), 256>>>(mkGA(x, LIN_, WxB, Bu, HD_, LIN_, GF_BIAS,
                                         WxB + (size_t)256 * HD_));

    // 3) Phase 1 by pairwise doubling (4 serial levels), squarings fused
    gemm_two<<<dim3(8, 136), 256>>>(
        mkGA(Bu, 2*HD_, Amat, D1, HD_, HD_, GF_ADDM, nullptr, nullptr, nullptr,
             Bu + HD_, 0, 2*HD_),
        mkGA(Amat, HD_, Amat, P0, HD_, HD_, 0), 128);
    gemm_two<<<dim3(8, 72), 256>>>(
        mkGA(D1, 2*HD_, P0, D2, HD_, HD_, GF_ADDM, nullptr, nullptr, nullptr,
             D1 + HD_, 0, 2*HD_),
        mkGA(P0, HD_, P0, P1, HD_, HD_, 0), 64);
    gemm_two<<<dim3(8, 40), 256>>>(
        mkGA(D2, 2*HD_, P1, D1, HD_, HD_, GF_ADDM, nullptr, nullptr, nullptr,
             D2 + HD_, 0, 2*HD_),
        mkGA(P1, HD_, P1, P2, HD_, HD_, 0), 32);
    gemm_two<<<dim3(8, 24), 256>>>(
        mkGA(D1, 2*HD_, P2, D2, HD_, HD_, GF_ADDM, nullptr, nullptr, nullptr,
             D1 + HD_, 0, 2*HD_),
        mkGA(P2, HD_, P2, P0, HD_, HD_, 0), 16);
    remapE<<<ROWS_, 256>>>(D2, FA + AP);

    // 4) Hillis-Steele inclusive prefix over 128 chunks (7 rounds),
    //    squaring P between rounds (fused segment).
    float* cur = FA; float* nxt = FB;
    float* Pk = P0; float* Po = P1;
    for (int r = 0; r < 7; r++) {
        const int s = 1 << r;
        GA pre = mkGA(cur + AP - (size_t)16 * s * HD_, HD_, Pk, nxt + AP,
                      HD_, HD_, GF_ADDM, nullptr, nullptr, nullptr, cur + AP);
        if (r < 6) {
            gemm_two<<<dim3(8, 24), 256>>>(pre, mkGA(Pk, HD_, Pk, Po, HD_, HD_, 0), 16);
            float* u = Pk; Pk = Po; Po = u;
        } else {
            gemm_one<<<dim3(8, 16), 256>>>(pre);
        }
        float* t = cur; cur = nxt; nxt = t;
    }

    // 5) Phase 2: persistent kernel, 16 grid-barrier-separated scan steps
    scan2<<<dim3(8, 16), 256>>>(cur, nxt, Amat, Bu, outH);

    // 6) z = x[:, -1, :] @ W_res + b_res + H_seq_pre[:, -1, :]
    sgemmKS<SF_BIAS | SF_ADD><<<16, 256>>>(x + (size_t)(SEQ_ - 1) * LIN_,
                                           (long)SEQ_ * LIN_,
                                           Wres, HD_, Z, HD_, bres,
                                           outH + (size_t)(SEQ_ - 1) * HD_,
                                           (long)SEQ_ * HD_, BATCH_, LIN_);
    // 7) LayerNorm
    ln16<<<BATCH_, 256>>>(Z, lng, lnb, HL);
    // 8) MLP head
    sgemmKS<SF_BIAS | SF_RELU><<<FMLP_ / 64, 256>>>(HL, HD_, W1, FMLP_, T, FMLP_,
                                                    b1, nullptr, 0, BATCH_, HD_);
    sgemmKS<SF_BIAS><<<HD_ / 64, 256>>>(T, FMLP_, W2, HD_, out0, HD_,
                                        b2, nullptr, 0, BATCH_, FMLP_);
}